// round 7
// baseline (speedup 1.0000x reference)
#include <cuda_runtime.h>
#include <cuda_bf16.h>

typedef __nv_bfloat16 bf16;
typedef unsigned int u32;
typedef unsigned long long u64;

// ---------------------------------------------------------------------------
// Problem constants: B=8, TQ=TK=2048, F=1024, H=1024
// ---------------------------------------------------------------------------
#define MTOT (16384LL * 1024)

static __device__ bf16  g_Ehi[MTOT],  g_Elo[MTOT];
static __device__ bf16  g_Xhi[MTOT],  g_Xlo[MTOT];
static __device__ bf16  g_Wq_hi[1024*1024], g_Wq_lo[1024*1024];
static __device__ bf16  g_Wk_hi[1024*1024], g_Wk_lo[1024*1024];
static __device__ bf16  g_Wv_hi[1024*1024], g_Wv_lo[1024*1024];
static __device__ bf16  g_Qhi[MTOT],  g_Qlo[MTOT];
static __device__ bf16  g_Khi[MTOT],  g_Klo[MTOT];
static __device__ bf16  g_Vhi[MTOT],  g_Vlo[MTOT];          // V [b*2048+t][1024]
static __device__ float g_S[8LL * 2048 * 2048];
static __device__ bf16  g_Phi[8LL * 2048 * 2048], g_Plo[8LL * 2048 * 2048];
static __device__ int   g_mask_mode;

// ---------------------------------------------------------------------------
// PTX helpers (sm_80-era features; legal under generic compute_103 target)
// ---------------------------------------------------------------------------
__device__ __forceinline__ u32 smem_u32(const void* p) {
    u32 a;
    asm("{ .reg .u64 t; cvta.to.shared.u64 t, %1; cvt.u32.u64 %0, t; }"
        : "=r"(a) : "l"(p));
    return a;
}
#define CP_ASYNC16(dst, src) \
    asm volatile("cp.async.cg.shared.global [%0], [%1], 16;" \
                 :: "r"(dst), "l"(src) : "memory")
#define CP_COMMIT() asm volatile("cp.async.commit_group;" ::: "memory")
#define CP_WAIT1()  asm volatile("cp.async.wait_group 1;" ::: "memory")
#define CP_WAIT0()  asm volatile("cp.async.wait_group 0;" ::: "memory")

__device__ __forceinline__ void ldsm_x4(u32& r0, u32& r1, u32& r2, u32& r3, u32 a) {
    asm volatile("ldmatrix.sync.aligned.m8n8.x4.shared.b16 {%0,%1,%2,%3}, [%4];"
                 : "=r"(r0), "=r"(r1), "=r"(r2), "=r"(r3) : "r"(a));
}
__device__ __forceinline__ void ldsm_x2(u32& r0, u32& r1, u32 a) {
    asm volatile("ldmatrix.sync.aligned.m8n8.x2.shared.b16 {%0,%1}, [%2];"
                 : "=r"(r0), "=r"(r1) : "r"(a));
}
__device__ __forceinline__ void ldsm_x2t(u32& r0, u32& r1, u32 a) {
    asm volatile("ldmatrix.sync.aligned.m8n8.x2.trans.shared.b16 {%0,%1}, [%2];"
                 : "=r"(r0), "=r"(r1) : "r"(a));
}
__device__ __forceinline__ void mma_bf16(float* c, const u32* a, const u32* b) {
    asm volatile(
        "mma.sync.aligned.m16n8k16.row.col.f32.bf16.bf16.f32 "
        "{%0,%1,%2,%3}, {%4,%5,%6,%7}, {%8,%9}, {%0,%1,%2,%3};"
        : "+f"(c[0]), "+f"(c[1]), "+f"(c[2]), "+f"(c[3])
        : "r"(a[0]), "r"(a[1]), "r"(a[2]), "r"(a[3]), "r"(b[0]), "r"(b[1]));
}

// ---------------------------------------------------------------------------
// GEMM: D[m,n] = sum_k A[m,k]*B'[k,n] via bf16x3 (Ahi*Bhi + Ahi*Blo + Alo*Bhi)
//   BT=true : B stored [N][K] (k-major rows)   -> ldmatrix
//   BT=false: B stored [K][N] (n-major rows)   -> ldmatrix.trans
//   MODE 0: hi/lo bf16 out + bias;   MODE 2: fp32 out * alpha
// CTA tile 128x256, BK=64, 2-stage cp.async pipeline, 512 threads
// (16 warps, 2x8 grid, warp tile 64x32), register frag double-buffering.
// ---------------------------------------------------------------------------
#define BM 128
#define BN 256
#define BKK 64
#define APITCH 72                            // 64 + 8 pad (bf16 units)
#define ABYTES (BM * APITCH * 2)             // 18432
#define BPITCH_T 72
#define BBYTES_T (BN * BPITCH_T * 2)         // 36864
#define BPITCH_N 264                         // 256 + 8 pad
#define BBYTES_N (BKK * BPITCH_N * 2)        // 33792

template <int MODE, bool BT>
__global__ void __launch_bounds__(512, 1)
gemm_mma(const bf16* __restrict__ Ahi, const bf16* __restrict__ Alo,
         const bf16* __restrict__ Bhi, const bf16* __restrict__ Blo,
         const float* __restrict__ bias,
         bf16* __restrict__ C0, bf16* __restrict__ C1, float* __restrict__ Cf,
         int lda, int ldb, int ldc, int K, float alpha,
         long long sA, long long sB, long long sC)
{
    constexpr int BBYTES  = BT ? BBYTES_T : BBYTES_N;
    constexpr int OFF_ALO = ABYTES;
    constexpr int OFF_BHI = 2 * ABYTES;
    constexpr int OFF_BLO = 2 * ABYTES + BBYTES;
    constexpr int STAGE   = 2 * ABYTES + 2 * BBYTES;

    extern __shared__ char smem[];
    const u32 sb = smem_u32(smem);

    const int tid  = threadIdx.x;
    const int wid  = tid >> 5, lane = tid & 31;
    const int wm   = wid & 1, wn = wid >> 1;          // 2 x 8 warp grid
    const long long z = blockIdx.z;
    Ahi += z * sA; Alo += z * sA;
    Bhi += z * sB; Blo += z * sB;

    const int m0 = blockIdx.y * BM;
    const int n0 = blockIdx.x * BN;

    // ---- loader geometry (BK=64, 512 threads) ----
    // A: 128 rows x 64 cols: row = tid>>2, chunk pair (tid&3)*16 elems.
    const int ar = tid >> 2, ac = (tid & 3) * 16;
    // B(BT): 256 rows x 64: row = tid>>1, half (tid&1)*32 elems (4 chunks).
    const int br = tid >> 1, bc = (tid & 1) * 32;
    // B(NN): 64 rows x 256: rows tid>>4 (+32), cols (tid&15)*16 elems.
    const int nr = tid >> 4, nc = (tid & 15) * 16;

    auto load_stage = [&](int t) {
        const long long kb = (long long)t * BKK;
        const u32 st = sb + (u32)((t & 1) * STAGE);
        {
            const long long g = (long long)(m0 + ar) * lda + kb + ac;
            const u32 d = st + (u32)(ar * APITCH + ac) * 2;
            CP_ASYNC16(d,                Ahi + g);
            CP_ASYNC16(d + 16,           Ahi + g + 8);
            CP_ASYNC16(d + OFF_ALO,      Alo + g);
            CP_ASYNC16(d + OFF_ALO + 16, Alo + g + 8);
        }
        if (BT) {
            const long long g = (long long)(n0 + br) * ldb + kb + bc;
            const u32 d = st + OFF_BHI + (u32)(br * BPITCH_T + bc) * 2;
#pragma unroll
            for (int c = 0; c < 4; c++) {
                CP_ASYNC16(d + c * 16,          Bhi + g + c * 8);
                CP_ASYNC16(d + BBYTES + c * 16, Blo + g + c * 8);
            }
        } else {
#pragma unroll
            for (int i = 0; i < 2; i++) {
                const int r = nr + i * 32;
                const long long g = (kb + r) * (long long)ldb + n0 + nc;
                const u32 d = st + OFF_BHI + (u32)(r * BPITCH_N + nc) * 2;
                CP_ASYNC16(d,               Bhi + g);
                CP_ASYNC16(d + 16,          Bhi + g + 8);
                CP_ASYNC16(d + BBYTES,      Blo + g);
                CP_ASYNC16(d + BBYTES + 16, Blo + g + 8);
            }
        }
    };

    // ---- ldmatrix per-lane offsets ----
    const int a_lr = (lane & 7) + ((lane >> 3) & 1) * 8;
    const int a_lk = (lane >> 4) * 8;
    u32 a_off[4];
#pragma unroll
    for (int mt = 0; mt < 4; mt++)
        a_off[mt] = (u32)((wm * 64 + mt * 16 + a_lr) * APITCH + a_lk) * 2;

    const int l16 = lane & 15;
    u32 b_off[4];
    if (BT) {
        const int b_nr = l16 & 7, b_k = (l16 >> 3) * 8;
#pragma unroll
        for (int nt = 0; nt < 4; nt++)
            b_off[nt] = (u32)((wn * 32 + nt * 8 + b_nr) * BPITCH_T + b_k) * 2;
    } else {
        const int b_kr = l16;      // 16 k-rows
#pragma unroll
        for (int nt = 0; nt < 4; nt++)
            b_off[nt] = (u32)(b_kr * BPITCH_N + wn * 32 + nt * 8) * 2;
    }

    float acc[4][4][4];
#pragma unroll
    for (int i = 0; i < 4; i++)
#pragma unroll
        for (int j = 0; j < 4; j++)
#pragma unroll
            for (int v = 0; v < 4; v++) acc[i][j][v] = 0.0f;

    // double-buffered fragments
    u32 ah[2][4][4], al[2][4][4], bh[2][4][2], bl[2][4][2];

    const int nst = K / BKK;

    load_stage(0); CP_COMMIT();

    for (int t = 0; t < nst; t++) {
        __syncthreads();                       // compute of t-1 fully done
        if (t + 1 < nst) {
            load_stage(t + 1); CP_COMMIT();
            CP_WAIT1();                        // stage t landed
        } else {
            CP_WAIT0();
        }
        __syncthreads();                       // stage t visible to all

        const u32 st  = sb + (u32)((t & 1) * STAGE);
        const u32 bAh = st, bAl = st + OFF_ALO;
        const u32 bBh = st + OFF_BHI, bBl = st + OFF_BLO;

        // prime frag buffer 0 (kk = 0)
        {
#pragma unroll
            for (int mt = 0; mt < 4; mt++) {
                ldsm_x4(ah[0][mt][0], ah[0][mt][1], ah[0][mt][2], ah[0][mt][3],
                        bAh + a_off[mt]);
                ldsm_x4(al[0][mt][0], al[0][mt][1], al[0][mt][2], al[0][mt][3],
                        bAl + a_off[mt]);
            }
#pragma unroll
            for (int nt = 0; nt < 4; nt++) {
                if (BT) {
                    ldsm_x2(bh[0][nt][0], bh[0][nt][1], bBh + b_off[nt]);
                    ldsm_x2(bl[0][nt][0], bl[0][nt][1], bBl + b_off[nt]);
                } else {
                    ldsm_x2t(bh[0][nt][0], bh[0][nt][1], bBh + b_off[nt]);
                    ldsm_x2t(bl[0][nt][0], bl[0][nt][1], bBl + b_off[nt]);
                }
            }
        }

#pragma unroll
        for (int kk = 0; kk < 4; kk++) {
            const int cur = kk & 1, nxt = cur ^ 1;
            if (kk < 3) {
                const u32 ak = (u32)((kk + 1) * 32);   // 16 bf16 in k
                const u32 bk = BT ? (u32)((kk + 1) * 32)
                                  : (u32)((kk + 1) * 16 * BPITCH_N * 2);
#pragma unroll
                for (int mt = 0; mt < 4; mt++) {
                    ldsm_x4(ah[nxt][mt][0], ah[nxt][mt][1], ah[nxt][mt][2],
                            ah[nxt][mt][3], bAh + a_off[mt] + ak);
                    ldsm_x4(al[nxt][mt][0], al[nxt][mt][1], al[nxt][mt][2],
                            al[nxt][mt][3], bAl + a_off[mt] + ak);
                }
#pragma unroll
                for (int nt = 0; nt < 4; nt++) {
                    if (BT) {
                        ldsm_x2(bh[nxt][nt][0], bh[nxt][nt][1], bBh + b_off[nt] + bk);
                        ldsm_x2(bl[nxt][nt][0], bl[nxt][nt][1], bBl + b_off[nt] + bk);
                    } else {
                        ldsm_x2t(bh[nxt][nt][0], bh[nxt][nt][1], bBh + b_off[nt] + bk);
                        ldsm_x2t(bl[nxt][nt][0], bl[nxt][nt][1], bBl + b_off[nt] + bk);
                    }
                }
            }
#pragma unroll
            for (int mt = 0; mt < 4; mt++)
#pragma unroll
                for (int nt = 0; nt < 4; nt++) {
                    mma_bf16(acc[mt][nt], ah[cur][mt], bh[cur][nt]);
                    mma_bf16(acc[mt][nt], ah[cur][mt], bl[cur][nt]);
                    mma_bf16(acc[mt][nt], al[cur][mt], bh[cur][nt]);
                }
        }
    }

    // ---- epilogue ----
    const int gr = lane >> 2, gc = (lane & 3) * 2;
#pragma unroll
    for (int mt = 0; mt < 4; mt++) {
#pragma unroll
        for (int nt = 0; nt < 4; nt++) {
            const int m_ = m0 + wm * 64 + mt * 16 + gr;
            const int n_ = n0 + wn * 32 + nt * 8 + gc;
            const float* a4 = acc[mt][nt];
            if (MODE == 0) {
                const float b0 = bias[n_], b1 = bias[n_ + 1];
#pragma unroll
                for (int h = 0; h < 2; h++) {
                    const float v0 = a4[2 * h]     + b0;
                    const float v1 = a4[2 * h + 1] + b1;
                    const bf16 h0 = __float2bfloat16(v0);
                    const bf16 h1 = __float2bfloat16(v1);
                    const bf16 l0 = __float2bfloat16(v0 - __bfloat162float(h0));
                    const bf16 l1 = __float2bfloat16(v1 - __bfloat162float(h1));
                    const long long o = (long long)(m_ + 8 * h) * ldc + n_;
                    *(__nv_bfloat162*)(C0 + o) = __nv_bfloat162(h0, h1);
                    *(__nv_bfloat162*)(C1 + o) = __nv_bfloat162(l0, l1);
                }
            } else {
                float* Cz = Cf + z * sC;
#pragma unroll
                for (int h = 0; h < 2; h++) {
                    const long long o = (long long)(m_ + 8 * h) * ldc + n_;
                    float2 v = make_float2(a4[2 * h] * alpha, a4[2 * h + 1] * alpha);
                    *(float2*)(Cz + o) = v;
                }
            }
        }
    }
}

// ---------------------------------------------------------------------------
// fp32 -> (hi, lo) bf16 split
// ---------------------------------------------------------------------------
__global__ void __launch_bounds__(256)
split_f32(const float4* __restrict__ in, bf16* __restrict__ hi,
          bf16* __restrict__ lo)
{
    const long long i = (long long)blockIdx.x * 256 + threadIdx.x;
    const float4 v = in[i];
    const bf16 h0 = __float2bfloat16(v.x), h1 = __float2bfloat16(v.y);
    const bf16 h2 = __float2bfloat16(v.z), h3 = __float2bfloat16(v.w);
    const bf16 l0 = __float2bfloat16(v.x - __bfloat162float(h0));
    const bf16 l1 = __float2bfloat16(v.y - __bfloat162float(h1));
    const bf16 l2 = __float2bfloat16(v.z - __bfloat162float(h2));
    const bf16 l3 = __float2bfloat16(v.w - __bfloat162float(h3));
    *(__nv_bfloat162*)&hi[i * 4]     = __nv_bfloat162(h0, h1);
    *(__nv_bfloat162*)&hi[i * 4 + 2] = __nv_bfloat162(h2, h3);
    *(__nv_bfloat162*)&lo[i * 4]     = __nv_bfloat162(l0, l1);
    *(__nv_bfloat162*)&lo[i * 4 + 2] = __nv_bfloat162(l2, l3);
}

// W [F=1024, H=1024] -> W^T split hi/lo [H, F]
__global__ void wt_split(const float* __restrict__ W, bf16* __restrict__ Thi,
                         bf16* __restrict__ Tlo)
{
    __shared__ float ts[32][33];
    const int tx = threadIdx.x, ty = threadIdx.y;
    ts[ty][tx] = W[(long long)(blockIdx.y * 32 + ty) * 1024 + blockIdx.x * 32 + tx];
    __syncthreads();
    const float x = ts[tx][ty];
    const long long o = (long long)(blockIdx.x * 32 + ty) * 1024 + blockIdx.y * 32 + tx;
    const bf16 h = __float2bfloat16(x);
    Thi[o] = h;
    Tlo[o] = __float2bfloat16(x - __bfloat162float(h));
}

// ---------------------------------------------------------------------------
// Mask dtype detection (bool may arrive as u8/i32/f32)
// ---------------------------------------------------------------------------
__global__ void detect_mask_kernel(const unsigned char* __restrict__ m)
{
    __shared__ int bad_i32, bad_f32;
    if (threadIdx.x == 0) { bad_i32 = 0; bad_f32 = 0; }
    __syncthreads();
    const unsigned int* w = (const unsigned int*)m;
    for (int i = threadIdx.x; i < 2048; i += 256) {
        unsigned int x = w[i];
        if (x != 0u && x != 1u)          bad_i32 = 1;
        if (x != 0u && x != 0x3F800000u) bad_f32 = 1;
    }
    __syncthreads();
    if (threadIdx.x == 0)
        g_mask_mode = bad_i32 ? (bad_f32 ? 0 : 2) : 1;
}

// ---------------------------------------------------------------------------
// Masked softmax over rows of S [B*TQ, 2048] -> P hi/lo bf16
// ---------------------------------------------------------------------------
__global__ void __launch_bounds__(256)
softmax_kernel(const float* __restrict__ S, const void* __restrict__ maskv,
               bf16* __restrict__ Phi, bf16* __restrict__ Plo)
{
    const int TK = 2048;
    const long long base = (long long)blockIdx.x * TK;
    const float* s = S + base;
    const int tid  = threadIdx.x;
    const int mode = g_mask_mode;

    float v[8];
    bool  keep[8];
#pragma unroll
    for (int i = 0; i < 8; i++) {
        const int idx = tid + i * 256;
        v[i] = s[idx];
        bool kp;
        if (mode == 1)      kp = ((const int*)maskv)[base + idx] != 0;
        else if (mode == 2) kp = ((const float*)maskv)[base + idx] != 0.0f;
        else                kp = ((const unsigned char*)maskv)[base + idx] != 0;
        keep[i] = kp;
    }

    float mx = -3.0e38f;
#pragma unroll
    for (int i = 0; i < 8; i++)
        if (keep[i]) mx = fmaxf(mx, v[i]);

    __shared__ float red[8];
#pragma unroll
    for (int o = 16; o > 0; o >>= 1)
        mx = fmaxf(mx, __shfl_xor_sync(0xffffffffu, mx, o));
    if ((tid & 31) == 0) red[tid >> 5] = mx;
    __syncthreads();
    float bm = red[0];
#pragma unroll
    for (int i = 1; i < 8; i++) bm = fmaxf(bm, red[i]);

    float sum = 0.0f;
#pragma unroll
    for (int i = 0; i < 8; i++) {
        const float e = keep[i] ? __expf(v[i] - bm) : 0.0f;
        v[i] = e;
        sum += e;
    }
#pragma unroll
    for (int o = 16; o > 0; o >>= 1)
        sum += __shfl_xor_sync(0xffffffffu, sum, o);
    __syncthreads();
    if ((tid & 31) == 0) red[tid >> 5] = sum;
    __syncthreads();
    float ts = 0.0f;
#pragma unroll
    for (int i = 0; i < 8; i++) ts += red[i];

    const float inv = 1.0f / ts;
#pragma unroll
    for (int i = 0; i < 8; i++) {
        const float p = v[i] * inv;
        const bf16 h = __float2bfloat16(p);
        const bf16 l = __float2bfloat16(p - __bfloat162float(h));
        const long long o = base + tid + i * 256;
        Phi[o] = h;
        Plo[o] = l;
    }
}

// ---------------------------------------------------------------------------
// kernel_launch
// ---------------------------------------------------------------------------
extern "C" void kernel_launch(void* const* d_in, const int* in_sizes, int n_in,
                              void* d_out, int out_size)
{
    (void)in_sizes; (void)n_in; (void)out_size;

    const float* query = (const float*)d_in[0];
    const float* enc   = (const float*)d_in[1];
    const unsigned char* mask = (const unsigned char*)d_in[2];
    const float* Wq = (const float*)d_in[3];
    const float* bq = (const float*)d_in[4];
    const float* Wk = (const float*)d_in[5];
    const float* bk = (const float*)d_in[6];
    const float* Wv = (const float*)d_in[7];
    const float* bv = (const float*)d_in[8];
    float* out = (float*)d_out;

    bf16 *Ehi, *Elo, *Xhi, *Xlo;
    bf16 *Wqh, *Wql, *Wkh, *Wkl, *Wvh, *Wvl;
    bf16 *Qh, *Ql, *Kh, *Kl, *Vh, *Vl, *Ph, *Pl;
    float* Sp;
    cudaGetSymbolAddress((void**)&Ehi, g_Ehi);   cudaGetSymbolAddress((void**)&Elo, g_Elo);
    cudaGetSymbolAddress((void**)&Xhi, g_Xhi);   cudaGetSymbolAddress((void**)&Xlo, g_Xlo);
    cudaGetSymbolAddress((void**)&Wqh, g_Wq_hi); cudaGetSymbolAddress((void**)&Wql, g_Wq_lo);
    cudaGetSymbolAddress((void**)&Wkh, g_Wk_hi); cudaGetSymbolAddress((void**)&Wkl, g_Wk_lo);
    cudaGetSymbolAddress((void**)&Wvh, g_Wv_hi); cudaGetSymbolAddress((void**)&Wvl, g_Wv_lo);
    cudaGetSymbolAddress((void**)&Qh,  g_Qhi);   cudaGetSymbolAddress((void**)&Ql,  g_Qlo);
    cudaGetSymbolAddress((void**)&Kh,  g_Khi);   cudaGetSymbolAddress((void**)&Kl,  g_Klo);
    cudaGetSymbolAddress((void**)&Vh,  g_Vhi);   cudaGetSymbolAddress((void**)&Vl,  g_Vlo);
    cudaGetSymbolAddress((void**)&Ph,  g_Phi);   cudaGetSymbolAddress((void**)&Pl,  g_Plo);
    cudaGetSymbolAddress((void**)&Sp,  g_S);

    constexpr int SMEM_T = 2 * (2 * ABYTES + 2 * BBYTES_T);   // 221184
    constexpr int SMEM_N = 2 * (2 * ABYTES + 2 * BBYTES_N);   // 208896
    cudaFuncSetAttribute(gemm_mma<0, true>,  cudaFuncAttributeMaxDynamicSharedMemorySize, SMEM_T);
    cudaFuncSetAttribute(gemm_mma<2, true>,  cudaFuncAttributeMaxDynamicSharedMemorySize, SMEM_T);
    cudaFuncSetAttribute(gemm_mma<2, false>, cudaFuncAttributeMaxDynamicSharedMemorySize, SMEM_N);

    const int T = 2048;

    // 1) split inputs to bf16 hi/lo
    split_f32<<<16384, 256>>>((const float4*)enc,   Ehi, Elo);
    split_f32<<<16384, 256>>>((const float4*)query, Xhi, Xlo);

    // 2) transpose+split weights
    dim3 wtg(32, 32), wtb(32, 32);
    wt_split<<<wtg, wtb>>>(Wq, Wqh, Wql);
    wt_split<<<wtg, wtb>>>(Wk, Wkh, Wkl);
    wt_split<<<wtg, wtb>>>(Wv, Wvh, Wvl);

    detect_mask_kernel<<<1, 256>>>(mask);

    // 3) projections: [16384,1024] @ Wt[1024(n),1024(k)]  (BT layout)
    dim3 gp(1024 / BN, 16384 / BM, 1);
    gemm_mma<0, true><<<gp, 512, SMEM_T>>>(Ehi, Elo, Wkh, Wkl, bk, Kh, Kl, nullptr,
                                           1024, 1024, 1024, 1024, 1.0f, 0, 0, 0);
    gemm_mma<0, true><<<gp, 512, SMEM_T>>>(Ehi, Elo, Wvh, Wvl, bv, Vh, Vl, nullptr,
                                           1024, 1024, 1024, 1024, 1.0f, 0, 0, 0);
    gemm_mma<0, true><<<gp, 512, SMEM_T>>>(Xhi, Xlo, Wqh, Wql, bq, Qh, Ql, nullptr,
                                           1024, 1024, 1024, 1024, 1.0f, 0, 0, 0);

    // 4) scores: per batch S = (Q K^T) / 32     (B = K, [TK][H] = BT layout)
    dim3 gs(T / BN, T / BM, 8);
    gemm_mma<2, true><<<gs, 512, SMEM_T>>>(Qh, Ql, Kh, Kl, nullptr, nullptr, nullptr, Sp,
                                           1024, 1024, 2048, 1024, 0.03125f,
                                           2048LL * 1024, 2048LL * 1024, 2048LL * 2048);

    // 5) masked softmax -> P hi/lo
    softmax_kernel<<<8 * T, 256>>>(Sp, (const void*)mask, Ph, Pl);

    // 6) output: per batch O = P @ V   (B = V, [TK(k)][H(n)] = NN layout, ldmatrix.trans)
    dim3 go(1024 / BN, T / BM, 8);
    gemm_mma<2, false><<<go, 512, SMEM_N>>>(Ph, Pl, Vh, Vl, nullptr, nullptr, nullptr, out,
                                            2048, 1024, 1024, 2048, 1.0f,
                                            2048LL * 2048, 2048LL * 1024, 2048LL * 1024);
}

// round 8
// speedup vs baseline: 1.3214x; 1.3214x over previous
#include <cuda_runtime.h>
#include <cuda_bf16.h>
#include <cuda_fp16.h>

typedef __nv_bfloat16 bf16;
typedef unsigned short h16;    // opaque 16-bit payload (bf16 or fp16 bits)
typedef unsigned int u32;
typedef unsigned long long u64;

// ---------------------------------------------------------------------------
// Problem constants: B=8, TQ=TK=2048, F=1024, H=1024
// ---------------------------------------------------------------------------
#define MTOT (16384LL * 1024)

static __device__ h16   g_Ehi[MTOT],  g_Elo[MTOT];            // bf16 bits
static __device__ h16   g_Xhi[MTOT],  g_Xlo[MTOT];            // bf16 bits
static __device__ h16   g_Wq_hi[1024*1024], g_Wq_lo[1024*1024];
static __device__ h16   g_Wk_hi[1024*1024], g_Wk_lo[1024*1024];
static __device__ h16   g_Wv_hi[1024*1024], g_Wv_lo[1024*1024];
static __device__ h16   g_Qhi[MTOT],  g_Qdead[MTOT];          // fp16 bits (lo unused)
static __device__ h16   g_Khi[MTOT],  g_Klo[MTOT];            // fp16 bits
static __device__ h16   g_Vhi[MTOT],  g_Vlo[MTOT];            // fp16 bits, [b*2048+t][1024]
static __device__ float g_S[8LL * 2048 * 2048];
static __device__ h16   g_Phi[8LL * 2048 * 2048];             // fp16 bits
static __device__ int   g_mask_mode;

// ---------------------------------------------------------------------------
// PTX helpers (sm_80-era; legal under generic compute_103 target)
// ---------------------------------------------------------------------------
__device__ __forceinline__ u32 smem_u32(const void* p) {
    u32 a;
    asm("{ .reg .u64 t; cvta.to.shared.u64 t, %1; cvt.u32.u64 %0, t; }"
        : "=r"(a) : "l"(p));
    return a;
}
#define CP_ASYNC16(dst, src) \
    asm volatile("cp.async.cg.shared.global [%0], [%1], 16;" \
                 :: "r"(dst), "l"(src) : "memory")
#define CP_COMMIT() asm volatile("cp.async.commit_group;" ::: "memory")
#define CP_WAIT1()  asm volatile("cp.async.wait_group 1;" ::: "memory")

__device__ __forceinline__ void ldsm_x4(u32& r0, u32& r1, u32& r2, u32& r3, u32 a) {
    asm volatile("ldmatrix.sync.aligned.m8n8.x4.shared.b16 {%0,%1,%2,%3}, [%4];"
                 : "=r"(r0), "=r"(r1), "=r"(r2), "=r"(r3) : "r"(a));
}
__device__ __forceinline__ void ldsm_x2(u32& r0, u32& r1, u32 a) {
    asm volatile("ldmatrix.sync.aligned.m8n8.x2.shared.b16 {%0,%1}, [%2];"
                 : "=r"(r0), "=r"(r1) : "r"(a));
}
__device__ __forceinline__ void ldsm_x2t(u32& r0, u32& r1, u32 a) {
    asm volatile("ldmatrix.sync.aligned.m8n8.x2.trans.shared.b16 {%0,%1}, [%2];"
                 : "=r"(r0), "=r"(r1) : "r"(a));
}
template <int DT>   // 0 = bf16, 1 = fp16
__device__ __forceinline__ void mma16(float* c, const u32* a, const u32* b) {
    if (DT == 0)
        asm volatile(
            "mma.sync.aligned.m16n8k16.row.col.f32.bf16.bf16.f32 "
            "{%0,%1,%2,%3}, {%4,%5,%6,%7}, {%8,%9}, {%0,%1,%2,%3};"
            : "+f"(c[0]), "+f"(c[1]), "+f"(c[2]), "+f"(c[3])
            : "r"(a[0]), "r"(a[1]), "r"(a[2]), "r"(a[3]), "r"(b[0]), "r"(b[1]));
    else
        asm volatile(
            "mma.sync.aligned.m16n8k16.row.col.f32.f16.f16.f32 "
            "{%0,%1,%2,%3}, {%4,%5,%6,%7}, {%8,%9}, {%0,%1,%2,%3};"
            : "+f"(c[0]), "+f"(c[1]), "+f"(c[2]), "+f"(c[3])
            : "r"(a[0]), "r"(a[1]), "r"(a[2]), "r"(a[3]), "r"(b[0]), "r"(b[1]));
}

// ---------------------------------------------------------------------------
// GEMM: D[m,n] = sum_k A[m,k]*B'[k,n]
//   TERMS=3: D = Ahi*Bhi + Ahi*Blo + Alo*Bhi   (A dual, B dual)
//   TERMS=2: D = Ahi*Bhi + Ahi*Blo             (A single, B dual)
//   BT=true : B stored [N][K] -> ldmatrix; BT=false: B [K][N] -> ldmatrix.trans
//   MODE 0: fp16 hi/lo out + bias;  MODE 2: fp32 out * alpha
// CTA tile 128x128, BK=64, 3-stage cp.async pipeline, 256 threads (8 warps
// 2x4), register frag double-buffering.
// ---------------------------------------------------------------------------
#define BM 128
#define BN 128
#define BKK 64
#define APITCH 72                            // 64 + 8 pad (16b units)
#define ABYTES (BM * APITCH * 2)             // 18432
#define BPITCH_T 72
#define BBYTES_T (BN * BPITCH_T * 2)         // 18432
#define BPITCH_N 136                         // 128 + 8 pad
#define BBYTES_N (BKK * BPITCH_N * 2)        // 17408

template <int MODE, bool BT, int TERMS, int DT>
__global__ void __launch_bounds__(256, 1)
gemm_mma(const h16* __restrict__ Ahi, const h16* __restrict__ Alo,
         const h16* __restrict__ Bhi, const h16* __restrict__ Blo,
         const float* __restrict__ bias,
         h16* __restrict__ C0, h16* __restrict__ C1, float* __restrict__ Cf,
         int lda, int ldb, int ldc, int K, float alpha,
         long long sA, long long sB, long long sC)
{
    constexpr int BBYTES  = BT ? BBYTES_T : BBYTES_N;
    constexpr int NA      = (TERMS == 3) ? 2 : 1;
    constexpr int OFF_BHI = NA * ABYTES;
    constexpr int OFF_BLO = NA * ABYTES + BBYTES;
    constexpr int STAGE   = NA * ABYTES + 2 * BBYTES;

    extern __shared__ char smem[];
    const u32 sb = smem_u32(smem);

    const int tid  = threadIdx.x;
    const int wid  = tid >> 5, lane = tid & 31;
    const int wm   = wid & 1, wn = wid >> 1;          // 2 x 4 warp grid
    const long long z = blockIdx.z;
    Ahi += z * sA; if (TERMS == 3) Alo += z * sA;
    Bhi += z * sB; Blo += z * sB;

    const int m0 = blockIdx.y * BM;
    const int n0 = blockIdx.x * BN;

    // ---- loader geometry (BK=64, 256 threads) ----
    const int ar0 = tid >> 2, ac = (tid & 3) * 16;
    const int nr0 = tid >> 4, nc = (tid & 15) * 8;

    auto load_stage = [&](int t) {
        const long long kb = (long long)t * BKK;
        const u32 st = sb + (u32)((t % 3) * STAGE);
#pragma unroll
        for (int i = 0; i < 2; i++) {
            const int r = ar0 + i * 64;
            const long long g = (long long)(m0 + r) * lda + kb + ac;
            const u32 d = st + (u32)(r * APITCH + ac) * 2;
            CP_ASYNC16(d,      Ahi + g);
            CP_ASYNC16(d + 16, Ahi + g + 8);
            if (TERMS == 3) {
                CP_ASYNC16(d + ABYTES,      Alo + g);
                CP_ASYNC16(d + ABYTES + 16, Alo + g + 8);
            }
        }
        if (BT) {
#pragma unroll
            for (int i = 0; i < 2; i++) {
                const int r = ar0 + i * 64;
                const long long g = (long long)(n0 + r) * ldb + kb + ac;
                const u32 d = st + OFF_BHI + (u32)(r * BPITCH_T + ac) * 2;
                CP_ASYNC16(d,               Bhi + g);
                CP_ASYNC16(d + 16,          Bhi + g + 8);
                CP_ASYNC16(d + BBYTES,      Blo + g);
                CP_ASYNC16(d + BBYTES + 16, Blo + g + 8);
            }
        } else {
#pragma unroll
            for (int i = 0; i < 4; i++) {
                const int r = nr0 + i * 16;
                const long long g = (kb + r) * (long long)ldb + n0 + nc;
                const u32 d = st + OFF_BHI + (u32)(r * BPITCH_N + nc) * 2;
                CP_ASYNC16(d,          Bhi + g);
                CP_ASYNC16(d + BBYTES, Blo + g);
            }
        }
    };

    // ---- ldmatrix per-lane offsets ----
    const int a_lr = (lane & 7) + ((lane >> 3) & 1) * 8;
    const int a_lk = (lane >> 4) * 8;
    u32 a_off[4];
#pragma unroll
    for (int mt = 0; mt < 4; mt++)
        a_off[mt] = (u32)((wm * 64 + mt * 16 + a_lr) * APITCH + a_lk) * 2;

    const int l16 = lane & 15;
    u32 b_off[4];
    if (BT) {
        const int b_nr = l16 & 7, b_k = (l16 >> 3) * 8;
#pragma unroll
        for (int nt = 0; nt < 4; nt++)
            b_off[nt] = (u32)((wn * 32 + nt * 8 + b_nr) * BPITCH_T + b_k) * 2;
    } else {
        const int b_kr = l16;      // 16 k-rows
#pragma unroll
        for (int nt = 0; nt < 4; nt++)
            b_off[nt] = (u32)(b_kr * BPITCH_N + wn * 32 + nt * 8) * 2;
    }

    float acc[4][4][4];
#pragma unroll
    for (int i = 0; i < 4; i++)
#pragma unroll
        for (int j = 0; j < 4; j++)
#pragma unroll
            for (int v = 0; v < 4; v++) acc[i][j][v] = 0.0f;

    // double-buffered fragments
    u32 ah[2][4][4], al[2][4][4], bh[2][4][2], bl[2][4][2];

    const int nst = K / BKK;

    load_stage(0); CP_COMMIT();
    load_stage(1); CP_COMMIT();

    for (int t = 0; t < nst; t++) {
        CP_WAIT1();
        __syncthreads();
        if (t + 2 < nst) load_stage(t + 2);
        CP_COMMIT();

        const u32 st  = sb + (u32)((t % 3) * STAGE);
        const u32 bAh = st, bAl = st + ABYTES;
        const u32 bBh = st + OFF_BHI, bBl = st + OFF_BLO;

        // prime frag buffer 0 (kk = 0)
        {
#pragma unroll
            for (int mt = 0; mt < 4; mt++) {
                ldsm_x4(ah[0][mt][0], ah[0][mt][1], ah[0][mt][2], ah[0][mt][3],
                        bAh + a_off[mt]);
                if (TERMS == 3)
                    ldsm_x4(al[0][mt][0], al[0][mt][1], al[0][mt][2], al[0][mt][3],
                            bAl + a_off[mt]);
            }
#pragma unroll
            for (int nt = 0; nt < 4; nt++) {
                if (BT) {
                    ldsm_x2(bh[0][nt][0], bh[0][nt][1], bBh + b_off[nt]);
                    ldsm_x2(bl[0][nt][0], bl[0][nt][1], bBl + b_off[nt]);
                } else {
                    ldsm_x2t(bh[0][nt][0], bh[0][nt][1], bBh + b_off[nt]);
                    ldsm_x2t(bl[0][nt][0], bl[0][nt][1], bBl + b_off[nt]);
                }
            }
        }

#pragma unroll
        for (int kk = 0; kk < 4; kk++) {
            const int cur = kk & 1, nxt = cur ^ 1;
            if (kk < 3) {
                const u32 ak = (u32)((kk + 1) * 32);
                const u32 bk = BT ? (u32)((kk + 1) * 32)
                                  : (u32)((kk + 1) * 16 * BPITCH_N * 2);
#pragma unroll
                for (int mt = 0; mt < 4; mt++) {
                    ldsm_x4(ah[nxt][mt][0], ah[nxt][mt][1], ah[nxt][mt][2],
                            ah[nxt][mt][3], bAh + a_off[mt] + ak);
                    if (TERMS == 3)
                        ldsm_x4(al[nxt][mt][0], al[nxt][mt][1], al[nxt][mt][2],
                                al[nxt][mt][3], bAl + a_off[mt] + ak);
                }
#pragma unroll
                for (int nt = 0; nt < 4; nt++) {
                    if (BT) {
                        ldsm_x2(bh[nxt][nt][0], bh[nxt][nt][1], bBh + b_off[nt] + bk);
                        ldsm_x2(bl[nxt][nt][0], bl[nxt][nt][1], bBl + b_off[nt] + bk);
                    } else {
                        ldsm_x2t(bh[nxt][nt][0], bh[nxt][nt][1], bBh + b_off[nt] + bk);
                        ldsm_x2t(bl[nxt][nt][0], bl[nxt][nt][1], bBl + b_off[nt] + bk);
                    }
                }
            }
#pragma unroll
            for (int mt = 0; mt < 4; mt++)
#pragma unroll
                for (int nt = 0; nt < 4; nt++) {
                    mma16<DT>(acc[mt][nt], ah[cur][mt], bh[cur][nt]);
                    mma16<DT>(acc[mt][nt], ah[cur][mt], bl[cur][nt]);
                    if (TERMS == 3)
                        mma16<DT>(acc[mt][nt], al[cur][mt], bh[cur][nt]);
                }
        }
    }

    // ---- epilogue ----
    const int gr = lane >> 2, gc = (lane & 3) * 2;
#pragma unroll
    for (int mt = 0; mt < 4; mt++) {
#pragma unroll
        for (int nt = 0; nt < 4; nt++) {
            const int m_ = m0 + wm * 64 + mt * 16 + gr;
            const int n_ = n0 + wn * 32 + nt * 8 + gc;
            const float* a4 = acc[mt][nt];
            if (MODE == 0) {
                const float b0 = bias[n_], b1 = bias[n_ + 1];
#pragma unroll
                for (int h = 0; h < 2; h++) {
                    const float v0 = a4[2 * h]     + b0;
                    const float v1 = a4[2 * h + 1] + b1;
                    const __half h0 = __float2half_rn(v0);
                    const __half h1 = __float2half_rn(v1);
                    const __half l0 = __float2half_rn(v0 - __half2float(h0));
                    const __half l1 = __float2half_rn(v1 - __half2float(h1));
                    const long long o = (long long)(m_ + 8 * h) * ldc + n_;
                    h16 hp[2] = { __half_as_ushort(h0), __half_as_ushort(h1) };
                    h16 lp[2] = { __half_as_ushort(l0), __half_as_ushort(l1) };
                    *(u32*)(C0 + o) = *(const u32*)hp;
                    *(u32*)(C1 + o) = *(const u32*)lp;
                }
            } else {
                float* Cz = Cf + z * sC;
#pragma unroll
                for (int h = 0; h < 2; h++) {
                    const long long o = (long long)(m_ + 8 * h) * ldc + n_;
                    float2 v = make_float2(a4[2 * h] * alpha, a4[2 * h + 1] * alpha);
                    *(float2*)(Cz + o) = v;
                }
            }
        }
    }
}

// ---------------------------------------------------------------------------
// fp32 -> (hi, lo) bf16 split (for projection inputs/weights)
// ---------------------------------------------------------------------------
__global__ void __launch_bounds__(256)
split_f32(const float4* __restrict__ in, h16* __restrict__ hi,
          h16* __restrict__ lo)
{
    const long long i = (long long)blockIdx.x * 256 + threadIdx.x;
    const float4 v = in[i];
    const bf16 h0 = __float2bfloat16(v.x), h1 = __float2bfloat16(v.y);
    const bf16 h2 = __float2bfloat16(v.z), h3 = __float2bfloat16(v.w);
    const bf16 l0 = __float2bfloat16(v.x - __bfloat162float(h0));
    const bf16 l1 = __float2bfloat16(v.y - __bfloat162float(h1));
    const bf16 l2 = __float2bfloat16(v.z - __bfloat162float(h2));
    const bf16 l3 = __float2bfloat16(v.w - __bfloat162float(h3));
    h16 hp[4] = { __bfloat16_as_ushort(h0), __bfloat16_as_ushort(h1),
                  __bfloat16_as_ushort(h2), __bfloat16_as_ushort(h3) };
    h16 lp[4] = { __bfloat16_as_ushort(l0), __bfloat16_as_ushort(l1),
                  __bfloat16_as_ushort(l2), __bfloat16_as_ushort(l3) };
    *(uint2*)&hi[i * 4] = *(const uint2*)hp;
    *(uint2*)&lo[i * 4] = *(const uint2*)lp;
}

// W [F=1024, H=1024] -> W^T split hi/lo bf16 [H, F]
__global__ void wt_split(const float* __restrict__ W, h16* __restrict__ Thi,
                         h16* __restrict__ Tlo)
{
    __shared__ float ts[32][33];
    const int tx = threadIdx.x, ty = threadIdx.y;
    ts[ty][tx] = W[(long long)(blockIdx.y * 32 + ty) * 1024 + blockIdx.x * 32 + tx];
    __syncthreads();
    const float x = ts[tx][ty];
    const long long o = (long long)(blockIdx.x * 32 + ty) * 1024 + blockIdx.y * 32 + tx;
    const bf16 h = __float2bfloat16(x);
    Thi[o] = __bfloat16_as_ushort(h);
    Tlo[o] = __bfloat16_as_ushort(__float2bfloat16(x - __bfloat162float(h)));
}

// ---------------------------------------------------------------------------
// Mask dtype detection (bool may arrive as u8/i32/f32)
// ---------------------------------------------------------------------------
__global__ void detect_mask_kernel(const unsigned char* __restrict__ m)
{
    __shared__ int bad_i32, bad_f32;
    if (threadIdx.x == 0) { bad_i32 = 0; bad_f32 = 0; }
    __syncthreads();
    const unsigned int* w = (const unsigned int*)m;
    for (int i = threadIdx.x; i < 2048; i += 256) {
        unsigned int x = w[i];
        if (x != 0u && x != 1u)          bad_i32 = 1;
        if (x != 0u && x != 0x3F800000u) bad_f32 = 1;
    }
    __syncthreads();
    if (threadIdx.x == 0)
        g_mask_mode = bad_i32 ? (bad_f32 ? 0 : 2) : 1;
}

// ---------------------------------------------------------------------------
// Masked softmax over rows of S [B*TQ, 2048] -> P single fp16
// ---------------------------------------------------------------------------
__global__ void __launch_bounds__(256)
softmax_kernel(const float* __restrict__ S, const void* __restrict__ maskv,
               h16* __restrict__ Phi)
{
    const int TK = 2048;
    const long long base = (long long)blockIdx.x * TK;
    const float* s = S + base;
    const int tid  = threadIdx.x;
    const int mode = g_mask_mode;

    float v[8];
    bool  keep[8];
#pragma unroll
    for (int i = 0; i < 8; i++) {
        const int idx = tid + i * 256;
        v[i] = s[idx];
        bool kp;
        if (mode == 1)      kp = ((const int*)maskv)[base + idx] != 0;
        else if (mode == 2) kp = ((const float*)maskv)[base + idx] != 0.0f;
        else                kp = ((const unsigned char*)maskv)[base + idx] != 0;
        keep[i] = kp;
    }

    float mx = -3.0e38f;
#pragma unroll
    for (int i = 0; i < 8; i++)
        if (keep[i]) mx = fmaxf(mx, v[i]);

    __shared__ float red[8];
#pragma unroll
    for (int o = 16; o > 0; o >>= 1)
        mx = fmaxf(mx, __shfl_xor_sync(0xffffffffu, mx, o));
    if ((tid & 31) == 0) red[tid >> 5] = mx;
    __syncthreads();
    float bm = red[0];
#pragma unroll
    for (int i = 1; i < 8; i++) bm = fmaxf(bm, red[i]);

    float sum = 0.0f;
#pragma unroll
    for (int i = 0; i < 8; i++) {
        const float e = keep[i] ? __expf(v[i] - bm) : 0.0f;
        v[i] = e;
        sum += e;
    }
#pragma unroll
    for (int o = 16; o > 0; o >>= 1)
        sum += __shfl_xor_sync(0xffffffffu, sum, o);
    __syncthreads();
    if ((tid & 31) == 0) red[tid >> 5] = sum;
    __syncthreads();
    float ts = 0.0f;
#pragma unroll
    for (int i = 0; i < 8; i++) ts += red[i];

    const float inv = 1.0f / ts;
#pragma unroll
    for (int i = 0; i < 8; i++)
        Phi[base + tid + i * 256] =
            __half_as_ushort(__float2half_rn(v[i] * inv));
}

// ---------------------------------------------------------------------------
// kernel_launch
// ---------------------------------------------------------------------------
extern "C" void kernel_launch(void* const* d_in, const int* in_sizes, int n_in,
                              void* d_out, int out_size)
{
    (void)in_sizes; (void)n_in; (void)out_size;

    const float* query = (const float*)d_in[0];
    const float* enc   = (const float*)d_in[1];
    const unsigned char* mask = (const unsigned char*)d_in[2];
    const float* Wq = (const float*)d_in[3];
    const float* bq = (const float*)d_in[4];
    const float* Wk = (const float*)d_in[5];
    const float* bk = (const float*)d_in[6];
    const float* Wv = (const float*)d_in[7];
    const float* bv = (const float*)d_in[8];
    float* out = (float*)d_out;

    h16 *Ehi, *Elo, *Xhi, *Xlo;
    h16 *Wqh, *Wql, *Wkh, *Wkl, *Wvh, *Wvl;
    h16 *Qh, *Qd, *Kh, *Kl, *Vh, *Vl, *Ph;
    float* Sp;
    cudaGetSymbolAddress((void**)&Ehi, g_Ehi);   cudaGetSymbolAddress((void**)&Elo, g_Elo);
    cudaGetSymbolAddress((void**)&Xhi, g_Xhi);   cudaGetSymbolAddress((void**)&Xlo, g_Xlo);
    cudaGetSymbolAddress((void**)&Wqh, g_Wq_hi); cudaGetSymbolAddress((void**)&Wql, g_Wq_lo);
    cudaGetSymbolAddress((void**)&Wkh, g_Wk_hi); cudaGetSymbolAddress((void**)&Wkl, g_Wk_lo);
    cudaGetSymbolAddress((void**)&Wvh, g_Wv_hi); cudaGetSymbolAddress((void**)&Wvl, g_Wv_lo);
    cudaGetSymbolAddress((void**)&Qh,  g_Qhi);   cudaGetSymbolAddress((void**)&Qd,  g_Qdead);
    cudaGetSymbolAddress((void**)&Kh,  g_Khi);   cudaGetSymbolAddress((void**)&Kl,  g_Klo);
    cudaGetSymbolAddress((void**)&Vh,  g_Vhi);   cudaGetSymbolAddress((void**)&Vl,  g_Vlo);
    cudaGetSymbolAddress((void**)&Ph,  g_Phi);
    cudaGetSymbolAddress((void**)&Sp,  g_S);

    constexpr int SMEM_PROJ = 3 * (2 * ABYTES + 2 * BBYTES_T);  // 221184
    constexpr int SMEM_SC   = 3 * (1 * ABYTES + 2 * BBYTES_T);  // 165888
    constexpr int SMEM_PV   = 3 * (1 * ABYTES + 2 * BBYTES_N);  // 159744
    cudaFuncSetAttribute(gemm_mma<0, true, 3, 0>,
                         cudaFuncAttributeMaxDynamicSharedMemorySize, SMEM_PROJ);
    cudaFuncSetAttribute(gemm_mma<2, true, 2, 1>,
                         cudaFuncAttributeMaxDynamicSharedMemorySize, SMEM_SC);
    cudaFuncSetAttribute(gemm_mma<2, false, 2, 1>,
                         cudaFuncAttributeMaxDynamicSharedMemorySize, SMEM_PV);

    const int T = 2048;

    // 1) split inputs to bf16 hi/lo
    split_f32<<<16384, 256>>>((const float4*)enc,   Ehi, Elo);
    split_f32<<<16384, 256>>>((const float4*)query, Xhi, Xlo);

    // 2) transpose+split weights (bf16)
    dim3 wtg(32, 32), wtb(32, 32);
    wt_split<<<wtg, wtb>>>(Wq, Wqh, Wql);
    wt_split<<<wtg, wtb>>>(Wk, Wkh, Wkl);
    wt_split<<<wtg, wtb>>>(Wv, Wvh, Wvl);

    detect_mask_kernel<<<1, 256>>>(mask);

    // 3) projections: bf16x3, fp16 hi/lo outputs
    dim3 gp(1024 / BN, 16384 / BM, 1);
    gemm_mma<0, true, 3, 0><<<gp, 256, SMEM_PROJ>>>(Ehi, Elo, Wkh, Wkl, bk,
        Kh, Kl, nullptr, 1024, 1024, 1024, 1024, 1.0f, 0, 0, 0);
    gemm_mma<0, true, 3, 0><<<gp, 256, SMEM_PROJ>>>(Ehi, Elo, Wvh, Wvl, bv,
        Vh, Vl, nullptr, 1024, 1024, 1024, 1024, 1.0f, 0, 0, 0);
    gemm_mma<0, true, 3, 0><<<gp, 256, SMEM_PROJ>>>(Xhi, Xlo, Wqh, Wql, bq,
        Qh, Qd, nullptr, 1024, 1024, 1024, 1024, 1.0f, 0, 0, 0);

    // 4) scores: fp16 2-term, S = (Qh (Kh+Kl)^T) / 32
    dim3 gs(T / BN, T / BM, 8);
    gemm_mma<2, true, 2, 1><<<gs, 256, SMEM_SC>>>(Qh, nullptr, Kh, Kl, nullptr,
        nullptr, nullptr, Sp, 1024, 1024, 2048, 1024, 0.03125f,
        2048LL * 1024, 2048LL * 1024, 2048LL * 2048);

    // 5) masked softmax -> P single fp16
    softmax_kernel<<<8 * T, 256>>>(Sp, (const void*)mask, Ph);

    // 6) output: fp16 2-term, O = Ph (Vh+Vl)   (V NN layout, ldmatrix.trans)
    dim3 go(1024 / BN, T / BM, 8);
    gemm_mma<2, false, 2, 1><<<go, 256, SMEM_PV>>>(Ph, nullptr, Vh, Vl, nullptr,
        nullptr, nullptr, out, 2048, 1024, 1024, 2048, 1.0f,
        2048LL * 2048, 2048LL * 1024, 2048LL * 1024);
}

// round 9
// speedup vs baseline: 1.5259x; 1.1547x over previous
#include <cuda_runtime.h>
#include <cuda_bf16.h>
#include <cuda_fp16.h>

typedef unsigned short h16;    // opaque 16-bit payload (fp16 bits)
typedef unsigned int u32;
typedef unsigned long long u64;

// ---------------------------------------------------------------------------
// Problem constants: B=8, TQ=TK=2048, F=1024, H=1024
// ---------------------------------------------------------------------------
#define MTOT (16384LL * 1024)

static __device__ h16   g_Ef[MTOT];                           // encoder fp16
static __device__ h16   g_Xf[MTOT];                           // query fp16
static __device__ h16   g_Wq_hi[1024*1024], g_Wq_lo[1024*1024];  // W^T fp16 hi/lo
static __device__ h16   g_Wk_hi[1024*1024], g_Wk_lo[1024*1024];
static __device__ h16   g_Wv_hi[1024*1024], g_Wv_lo[1024*1024];
static __device__ h16   g_Qhi[MTOT],  g_Qdead[MTOT];          // fp16 (lo unused)
static __device__ h16   g_Khi[MTOT],  g_Klo[MTOT];            // fp16 hi/lo
static __device__ h16   g_Vhi[MTOT],  g_Vlo[MTOT];            // fp16 hi/lo [b*2048+t][1024]
static __device__ float g_S[8LL * 2048 * 2048];
static __device__ h16   g_Phi[8LL * 2048 * 2048];             // fp16
static __device__ int   g_mask_mode;

// ---------------------------------------------------------------------------
// PTX helpers (sm_80-era; legal under generic compute_103 target)
// ---------------------------------------------------------------------------
__device__ __forceinline__ u32 smem_u32(const void* p) {
    u32 a;
    asm("{ .reg .u64 t; cvta.to.shared.u64 t, %1; cvt.u32.u64 %0, t; }"
        : "=r"(a) : "l"(p));
    return a;
}
#define CP_ASYNC16(dst, src) \
    asm volatile("cp.async.cg.shared.global [%0], [%1], 16;" \
                 :: "r"(dst), "l"(src) : "memory")
#define CP_COMMIT() asm volatile("cp.async.commit_group;" ::: "memory")
#define CP_WAIT1()  asm volatile("cp.async.wait_group 1;" ::: "memory")

__device__ __forceinline__ void ldsm_x4(u32& r0, u32& r1, u32& r2, u32& r3, u32 a) {
    asm volatile("ldmatrix.sync.aligned.m8n8.x4.shared.b16 {%0,%1,%2,%3}, [%4];"
                 : "=r"(r0), "=r"(r1), "=r"(r2), "=r"(r3) : "r"(a));
}
__device__ __forceinline__ void ldsm_x2(u32& r0, u32& r1, u32 a) {
    asm volatile("ldmatrix.sync.aligned.m8n8.x2.shared.b16 {%0,%1}, [%2];"
                 : "=r"(r0), "=r"(r1) : "r"(a));
}
__device__ __forceinline__ void ldsm_x2t(u32& r0, u32& r1, u32 a) {
    asm volatile("ldmatrix.sync.aligned.m8n8.x2.trans.shared.b16 {%0,%1}, [%2];"
                 : "=r"(r0), "=r"(r1) : "r"(a));
}
__device__ __forceinline__ void mma_f16(float* c, const u32* a, const u32* b) {
    asm volatile(
        "mma.sync.aligned.m16n8k16.row.col.f32.f16.f16.f32 "
        "{%0,%1,%2,%3}, {%4,%5,%6,%7}, {%8,%9}, {%0,%1,%2,%3};"
        : "+f"(c[0]), "+f"(c[1]), "+f"(c[2]), "+f"(c[3])
        : "r"(a[0]), "r"(a[1]), "r"(a[2]), "r"(a[3]), "r"(b[0]), "r"(b[1]));
}

// ---------------------------------------------------------------------------
// GEMM: D[m,n] = sum_k A[m,k]*(Bhi+Blo)'[k,n]    (fp16 2-term)
//   BT=true : B stored [N][K] -> ldmatrix; BT=false: B [K][N] -> ldmatrix.trans
//   MODE 0: fp16 hi/lo out + bias;  MODE 2: fp32 out * alpha
// CTA tile 128x128, BK=64, 3-stage cp.async pipeline, 256 threads (8 warps
// 2x4), register frag double-buffering.
// ---------------------------------------------------------------------------
#define BM 128
#define BN 128
#define BKK 64
#define APITCH 72                            // 64 + 8 pad (16b units)
#define ABYTES (BM * APITCH * 2)             // 18432
#define BPITCH_T 72
#define BBYTES_T (BN * BPITCH_T * 2)         // 18432
#define BPITCH_N 136                         // 128 + 8 pad
#define BBYTES_N (BKK * BPITCH_N * 2)        // 17408

template <int MODE, bool BT>
__global__ void __launch_bounds__(256, 1)
gemm_mma(const h16* __restrict__ A,
         const h16* __restrict__ Bhi, const h16* __restrict__ Blo,
         const float* __restrict__ bias,
         h16* __restrict__ C0, h16* __restrict__ C1, float* __restrict__ Cf,
         int lda, int ldb, int ldc, int K, float alpha,
         long long sA, long long sB, long long sC)
{
    constexpr int BBYTES  = BT ? BBYTES_T : BBYTES_N;
    constexpr int OFF_BHI = ABYTES;
    constexpr int OFF_BLO = ABYTES + BBYTES;
    constexpr int STAGE   = ABYTES + 2 * BBYTES;

    extern __shared__ char smem[];
    const u32 sb = smem_u32(smem);

    const int tid  = threadIdx.x;
    const int wid  = tid >> 5, lane = tid & 31;
    const int wm   = wid & 1, wn = wid >> 1;          // 2 x 4 warp grid
    const long long z = blockIdx.z;
    A += z * sA;
    Bhi += z * sB; Blo += z * sB;

    const int m0 = blockIdx.y * BM;
    const int n0 = blockIdx.x * BN;

    // ---- loader geometry (BK=64, 256 threads) ----
    const int ar0 = tid >> 2, ac = (tid & 3) * 16;
    const int nr0 = tid >> 4, nc = (tid & 15) * 8;

    auto load_stage = [&](int t) {
        const long long kb = (long long)t * BKK;
        const u32 st = sb + (u32)((t % 3) * STAGE);
#pragma unroll
        for (int i = 0; i < 2; i++) {
            const int r = ar0 + i * 64;
            const long long g = (long long)(m0 + r) * lda + kb + ac;
            const u32 d = st + (u32)(r * APITCH + ac) * 2;
            CP_ASYNC16(d,      A + g);
            CP_ASYNC16(d + 16, A + g + 8);
        }
        if (BT) {
#pragma unroll
            for (int i = 0; i < 2; i++) {
                const int r = ar0 + i * 64;
                const long long g = (long long)(n0 + r) * ldb + kb + ac;
                const u32 d = st + OFF_BHI + (u32)(r * BPITCH_T + ac) * 2;
                CP_ASYNC16(d,               Bhi + g);
                CP_ASYNC16(d + 16,          Bhi + g + 8);
                CP_ASYNC16(d + BBYTES,      Blo + g);
                CP_ASYNC16(d + BBYTES + 16, Blo + g + 8);
            }
        } else {
#pragma unroll
            for (int i = 0; i < 4; i++) {
                const int r = nr0 + i * 16;
                const long long g = (kb + r) * (long long)ldb + n0 + nc;
                const u32 d = st + OFF_BHI + (u32)(r * BPITCH_N + nc) * 2;
                CP_ASYNC16(d,          Bhi + g);
                CP_ASYNC16(d + BBYTES, Blo + g);
            }
        }
    };

    // ---- ldmatrix per-lane offsets ----
    const int a_lr = (lane & 7) + ((lane >> 3) & 1) * 8;
    const int a_lk = (lane >> 4) * 8;
    u32 a_off[4];
#pragma unroll
    for (int mt = 0; mt < 4; mt++)
        a_off[mt] = (u32)((wm * 64 + mt * 16 + a_lr) * APITCH + a_lk) * 2;

    const int l16 = lane & 15;
    u32 b_off[4];
    if (BT) {
        const int b_nr = l16 & 7, b_k = (l16 >> 3) * 8;
#pragma unroll
        for (int nt = 0; nt < 4; nt++)
            b_off[nt] = (u32)((wn * 32 + nt * 8 + b_nr) * BPITCH_T + b_k) * 2;
    } else {
        const int b_kr = l16;      // 16 k-rows
#pragma unroll
        for (int nt = 0; nt < 4; nt++)
            b_off[nt] = (u32)(b_kr * BPITCH_N + wn * 32 + nt * 8) * 2;
    }

    float acc[4][4][4];
#pragma unroll
    for (int i = 0; i < 4; i++)
#pragma unroll
        for (int j = 0; j < 4; j++)
#pragma unroll
            for (int v = 0; v < 4; v++) acc[i][j][v] = 0.0f;

    // double-buffered fragments
    u32 ah[2][4][4], bh[2][4][2], bl[2][4][2];

    const int nst = K / BKK;

    load_stage(0); CP_COMMIT();
    load_stage(1); CP_COMMIT();

    for (int t = 0; t < nst; t++) {
        CP_WAIT1();
        __syncthreads();
        if (t + 2 < nst) load_stage(t + 2);
        CP_COMMIT();

        const u32 st  = sb + (u32)((t % 3) * STAGE);
        const u32 bAh = st;
        const u32 bBh = st + OFF_BHI, bBl = st + OFF_BLO;

        // prime frag buffer 0 (kk = 0)
        {
#pragma unroll
            for (int mt = 0; mt < 4; mt++)
                ldsm_x4(ah[0][mt][0], ah[0][mt][1], ah[0][mt][2], ah[0][mt][3],
                        bAh + a_off[mt]);
#pragma unroll
            for (int nt = 0; nt < 4; nt++) {
                if (BT) {
                    ldsm_x2(bh[0][nt][0], bh[0][nt][1], bBh + b_off[nt]);
                    ldsm_x2(bl[0][nt][0], bl[0][nt][1], bBl + b_off[nt]);
                } else {
                    ldsm_x2t(bh[0][nt][0], bh[0][nt][1], bBh + b_off[nt]);
                    ldsm_x2t(bl[0][nt][0], bl[0][nt][1], bBl + b_off[nt]);
                }
            }
        }

#pragma unroll
        for (int kk = 0; kk < 4; kk++) {
            const int cur = kk & 1, nxt = cur ^ 1;
            if (kk < 3) {
                const u32 ak = (u32)((kk + 1) * 32);
                const u32 bk = BT ? (u32)((kk + 1) * 32)
                                  : (u32)((kk + 1) * 16 * BPITCH_N * 2);
#pragma unroll
                for (int mt = 0; mt < 4; mt++)
                    ldsm_x4(ah[nxt][mt][0], ah[nxt][mt][1], ah[nxt][mt][2],
                            ah[nxt][mt][3], bAh + a_off[mt] + ak);
#pragma unroll
                for (int nt = 0; nt < 4; nt++) {
                    if (BT) {
                        ldsm_x2(bh[nxt][nt][0], bh[nxt][nt][1], bBh + b_off[nt] + bk);
                        ldsm_x2(bl[nxt][nt][0], bl[nxt][nt][1], bBl + b_off[nt] + bk);
                    } else {
                        ldsm_x2t(bh[nxt][nt][0], bh[nxt][nt][1], bBh + b_off[nt] + bk);
                        ldsm_x2t(bl[nxt][nt][0], bl[nxt][nt][1], bBl + b_off[nt] + bk);
                    }
                }
            }
#pragma unroll
            for (int mt = 0; mt < 4; mt++)
#pragma unroll
                for (int nt = 0; nt < 4; nt++) {
                    mma_f16(acc[mt][nt], ah[cur][mt], bh[cur][nt]);
                    mma_f16(acc[mt][nt], ah[cur][mt], bl[cur][nt]);
                }
        }
    }

    // ---- epilogue ----
    const int gr = lane >> 2, gc = (lane & 3) * 2;
#pragma unroll
    for (int mt = 0; mt < 4; mt++) {
#pragma unroll
        for (int nt = 0; nt < 4; nt++) {
            const int m_ = m0 + wm * 64 + mt * 16 + gr;
            const int n_ = n0 + wn * 32 + nt * 8 + gc;
            const float* a4 = acc[mt][nt];
            if (MODE == 0) {
                const float b0 = bias[n_], b1 = bias[n_ + 1];
#pragma unroll
                for (int h = 0; h < 2; h++) {
                    const float v0 = a4[2 * h]     + b0;
                    const float v1 = a4[2 * h + 1] + b1;
                    const __half h0 = __float2half_rn(v0);
                    const __half h1 = __float2half_rn(v1);
                    const __half l0 = __float2half_rn(v0 - __half2float(h0));
                    const __half l1 = __float2half_rn(v1 - __half2float(h1));
                    const long long o = (long long)(m_ + 8 * h) * ldc + n_;
                    h16 hp[2] = { __half_as_ushort(h0), __half_as_ushort(h1) };
                    h16 lp[2] = { __half_as_ushort(l0), __half_as_ushort(l1) };
                    *(u32*)(C0 + o) = *(const u32*)hp;
                    *(u32*)(C1 + o) = *(const u32*)lp;
                }
            } else {
                float* Cz = Cf + z * sC;
#pragma unroll
                for (int h = 0; h < 2; h++) {
                    const long long o = (long long)(m_ + 8 * h) * ldc + n_;
                    float2 v = make_float2(a4[2 * h] * alpha, a4[2 * h + 1] * alpha);
                    *(float2*)(Cz + o) = v;
                }
            }
        }
    }
}

// ---------------------------------------------------------------------------
// fp32 -> single fp16 conversion (projection activations)
// ---------------------------------------------------------------------------
__global__ void __launch_bounds__(256)
conv_f16(const float4* __restrict__ in, h16* __restrict__ out)
{
    const long long i = (long long)blockIdx.x * 256 + threadIdx.x;
    const float4 v = in[i];
    h16 p[4] = { __half_as_ushort(__float2half_rn(v.x)),
                 __half_as_ushort(__float2half_rn(v.y)),
                 __half_as_ushort(__float2half_rn(v.z)),
                 __half_as_ushort(__float2half_rn(v.w)) };
    *(uint2*)&out[i * 4] = *(const uint2*)p;
}

// W [F=1024, H=1024] -> W^T split hi/lo fp16 [H, F]
__global__ void wt_split(const float* __restrict__ W, h16* __restrict__ Thi,
                         h16* __restrict__ Tlo)
{
    __shared__ float ts[32][33];
    const int tx = threadIdx.x, ty = threadIdx.y;
    ts[ty][tx] = W[(long long)(blockIdx.y * 32 + ty) * 1024 + blockIdx.x * 32 + tx];
    __syncthreads();
    const float x = ts[tx][ty];
    const long long o = (long long)(blockIdx.x * 32 + ty) * 1024 + blockIdx.y * 32 + tx;
    const __half h = __float2half_rn(x);
    Thi[o] = __half_as_ushort(h);
    Tlo[o] = __half_as_ushort(__float2half_rn(x - __half2float(h)));
}

// ---------------------------------------------------------------------------
// Mask dtype detection (bool may arrive as u8/i32/f32)
// ---------------------------------------------------------------------------
__global__ void detect_mask_kernel(const unsigned char* __restrict__ m)
{
    __shared__ int bad_i32, bad_f32;
    if (threadIdx.x == 0) { bad_i32 = 0; bad_f32 = 0; }
    __syncthreads();
    const unsigned int* w = (const unsigned int*)m;
    for (int i = threadIdx.x; i < 2048; i += 256) {
        unsigned int x = w[i];
        if (x != 0u && x != 1u)          bad_i32 = 1;
        if (x != 0u && x != 0x3F800000u) bad_f32 = 1;
    }
    __syncthreads();
    if (threadIdx.x == 0)
        g_mask_mode = bad_i32 ? (bad_f32 ? 0 : 2) : 1;
}

// ---------------------------------------------------------------------------
// Masked softmax over rows of S [B*TQ, 2048] -> P single fp16
// ---------------------------------------------------------------------------
__global__ void __launch_bounds__(256)
softmax_kernel(const float* __restrict__ S, const void* __restrict__ maskv,
               h16* __restrict__ Phi)
{
    const int TK = 2048;
    const long long base = (long long)blockIdx.x * TK;
    const float* s = S + base;
    const int tid  = threadIdx.x;
    const int mode = g_mask_mode;

    float v[8];
    bool  keep[8];
#pragma unroll
    for (int i = 0; i < 8; i++) {
        const int idx = tid + i * 256;
        v[i] = s[idx];
        bool kp;
        if (mode == 1)      kp = ((const int*)maskv)[base + idx] != 0;
        else if (mode == 2) kp = ((const float*)maskv)[base + idx] != 0.0f;
        else                kp = ((const unsigned char*)maskv)[base + idx] != 0;
        keep[i] = kp;
    }

    float mx = -3.0e38f;
#pragma unroll
    for (int i = 0; i < 8; i++)
        if (keep[i]) mx = fmaxf(mx, v[i]);

    __shared__ float red[8];
#pragma unroll
    for (int o = 16; o > 0; o >>= 1)
        mx = fmaxf(mx, __shfl_xor_sync(0xffffffffu, mx, o));
    if ((tid & 31) == 0) red[tid >> 5] = mx;
    __syncthreads();
    float bm = red[0];
#pragma unroll
    for (int i = 1; i < 8; i++) bm = fmaxf(bm, red[i]);

    float sum = 0.0f;
#pragma unroll
    for (int i = 0; i < 8; i++) {
        const float e = keep[i] ? __expf(v[i] - bm) : 0.0f;
        v[i] = e;
        sum += e;
    }
#pragma unroll
    for (int o = 16; o > 0; o >>= 1)
        sum += __shfl_xor_sync(0xffffffffu, sum, o);
    __syncthreads();
    if ((tid & 31) == 0) red[tid >> 5] = sum;
    __syncthreads();
    float ts = 0.0f;
#pragma unroll
    for (int i = 0; i < 8; i++) ts += red[i];

    const float inv = 1.0f / ts;
#pragma unroll
    for (int i = 0; i < 8; i++)
        Phi[base + tid + i * 256] =
            __half_as_ushort(__float2half_rn(v[i] * inv));
}

// ---------------------------------------------------------------------------
// kernel_launch
// ---------------------------------------------------------------------------
extern "C" void kernel_launch(void* const* d_in, const int* in_sizes, int n_in,
                              void* d_out, int out_size)
{
    (void)in_sizes; (void)n_in; (void)out_size;

    const float* query = (const float*)d_in[0];
    const float* enc   = (const float*)d_in[1];
    const unsigned char* mask = (const unsigned char*)d_in[2];
    const float* Wq = (const float*)d_in[3];
    const float* bq = (const float*)d_in[4];
    const float* Wk = (const float*)d_in[5];
    const float* bk = (const float*)d_in[6];
    const float* Wv = (const float*)d_in[7];
    const float* bv = (const float*)d_in[8];
    float* out = (float*)d_out;

    h16 *Ef, *Xf;
    h16 *Wqh, *Wql, *Wkh, *Wkl, *Wvh, *Wvl;
    h16 *Qh, *Qd, *Kh, *Kl, *Vh, *Vl, *Ph;
    float* Sp;
    cudaGetSymbolAddress((void**)&Ef,  g_Ef);
    cudaGetSymbolAddress((void**)&Xf,  g_Xf);
    cudaGetSymbolAddress((void**)&Wqh, g_Wq_hi); cudaGetSymbolAddress((void**)&Wql, g_Wq_lo);
    cudaGetSymbolAddress((void**)&Wkh, g_Wk_hi); cudaGetSymbolAddress((void**)&Wkl, g_Wk_lo);
    cudaGetSymbolAddress((void**)&Wvh, g_Wv_hi); cudaGetSymbolAddress((void**)&Wvl, g_Wv_lo);
    cudaGetSymbolAddress((void**)&Qh,  g_Qhi);   cudaGetSymbolAddress((void**)&Qd,  g_Qdead);
    cudaGetSymbolAddress((void**)&Kh,  g_Khi);   cudaGetSymbolAddress((void**)&Kl,  g_Klo);
    cudaGetSymbolAddress((void**)&Vh,  g_Vhi);   cudaGetSymbolAddress((void**)&Vl,  g_Vlo);
    cudaGetSymbolAddress((void**)&Ph,  g_Phi);
    cudaGetSymbolAddress((void**)&Sp,  g_S);

    constexpr int SMEM_T = 3 * (ABYTES + 2 * BBYTES_T);   // 165888
    constexpr int SMEM_N = 3 * (ABYTES + 2 * BBYTES_N);   // 159744
    cudaFuncSetAttribute(gemm_mma<0, true>,
                         cudaFuncAttributeMaxDynamicSharedMemorySize, SMEM_T);
    cudaFuncSetAttribute(gemm_mma<2, true>,
                         cudaFuncAttributeMaxDynamicSharedMemorySize, SMEM_T);
    cudaFuncSetAttribute(gemm_mma<2, false>,
                         cudaFuncAttributeMaxDynamicSharedMemorySize, SMEM_N);

    const int T = 2048;

    // 1) convert activations to single fp16
    conv_f16<<<16384, 256>>>((const float4*)enc,   Ef);
    conv_f16<<<16384, 256>>>((const float4*)query, Xf);

    // 2) transpose+split weights (fp16 hi/lo)
    dim3 wtg(32, 32), wtb(32, 32);
    wt_split<<<wtg, wtb>>>(Wq, Wqh, Wql);
    wt_split<<<wtg, wtb>>>(Wk, Wkh, Wkl);
    wt_split<<<wtg, wtb>>>(Wv, Wvh, Wvl);

    detect_mask_kernel<<<1, 256>>>(mask);

    // 3) projections: fp16 2-term, fp16 hi/lo outputs
    dim3 gp(1024 / BN, 16384 / BM, 1);
    gemm_mma<0, true><<<gp, 256, SMEM_T>>>(Ef, Wkh, Wkl, bk,
        Kh, Kl, nullptr, 1024, 1024, 1024, 1024, 1.0f, 0, 0, 0);
    gemm_mma<0, true><<<gp, 256, SMEM_T>>>(Ef, Wvh, Wvl, bv,
        Vh, Vl, nullptr, 1024, 1024, 1024, 1024, 1.0f, 0, 0, 0);
    gemm_mma<0, true><<<gp, 256, SMEM_T>>>(Xf, Wqh, Wql, bq,
        Qh, Qd, nullptr, 1024, 1024, 1024, 1024, 1.0f, 0, 0, 0);

    // 4) scores: fp16 2-term, S = (Qh (Kh+Kl)^T) / 32
    dim3 gs(T / BN, T / BM, 8);
    gemm_mma<2, true><<<gs, 256, SMEM_T>>>(Qh, Kh, Kl, nullptr,
        nullptr, nullptr, Sp, 1024, 1024, 2048, 1024, 0.03125f,
        2048LL * 1024, 2048LL * 1024, 2048LL * 2048);

    // 5) masked softmax -> P single fp16
    softmax_kernel<<<8 * T, 256>>>(Sp, (const void*)mask, Ph);

    // 6) output: fp16 2-term, O = Ph (Vh+Vl)   (V NN layout, ldmatrix.trans)
    dim3 go(1024 / BN, T / BM, 8);
    gemm_mma<2, false><<<go, 256, SMEM_N>>>(Ph, Vh, Vl, nullptr,
        nullptr, nullptr, out, 2048, 1024, 1024, 2048, 1.0f,
        2048LL * 2048, 2048LL * 1024, 2048LL * 1024);
}

// round 10
// speedup vs baseline: 1.9191x; 1.2577x over previous
#include <cuda_runtime.h>
#include <cuda_fp16.h>

typedef unsigned short h16;    // opaque 16-bit payload (fp16 bits)
typedef unsigned int u32;
typedef unsigned long long u64;

// ---------------------------------------------------------------------------
// Problem constants: B=8, TQ=TK=2048, F=1024, H=1024
// ---------------------------------------------------------------------------
#define MTOT (16384LL * 1024)

static __device__ h16   g_Ef[MTOT];                           // encoder fp16
static __device__ h16   g_Xf[MTOT];                           // query fp16
static __device__ h16   g_Wq_hi[1024*1024], g_Wq_lo[1024*1024];  // W^T fp16 hi/lo
static __device__ h16   g_Wk_hi[1024*1024], g_Wk_lo[1024*1024];
static __device__ h16   g_Wv_hi[1024*1024], g_Wv_lo[1024*1024];
static __device__ h16   g_Q[MTOT];                            // fp16
static __device__ h16   g_K[MTOT];                            // fp16
static __device__ h16   g_V[MTOT];                            // fp16 [b*2048+t][1024]
static __device__ float g_S[8LL * 2048 * 2048];
static __device__ h16   g_P[8LL * 2048 * 2048];               // fp16
static __device__ int   g_mask_mode;

// ---------------------------------------------------------------------------
// PTX helpers (sm_80-era; legal under generic compute_103 target)
// ---------------------------------------------------------------------------
__device__ __forceinline__ u32 smem_u32(const void* p) {
    u32 a;
    asm("{ .reg .u64 t; cvta.to.shared.u64 t, %1; cvt.u32.u64 %0, t; }"
        : "=r"(a) : "l"(p));
    return a;
}
#define CP_ASYNC16(dst, src) \
    asm volatile("cp.async.cg.shared.global [%0], [%1], 16;" \
                 :: "r"(dst), "l"(src) : "memory")
#define CP_COMMIT() asm volatile("cp.async.commit_group;" ::: "memory")
#define CP_WAIT1()  asm volatile("cp.async.wait_group 1;" ::: "memory")

__device__ __forceinline__ void ldsm_x4(u32& r0, u32& r1, u32& r2, u32& r3, u32 a) {
    asm volatile("ldmatrix.sync.aligned.m8n8.x4.shared.b16 {%0,%1,%2,%3}, [%4];"
                 : "=r"(r0), "=r"(r1), "=r"(r2), "=r"(r3) : "r"(a));
}
__device__ __forceinline__ void ldsm_x2(u32& r0, u32& r1, u32 a) {
    asm volatile("ldmatrix.sync.aligned.m8n8.x2.shared.b16 {%0,%1}, [%2];"
                 : "=r"(r0), "=r"(r1) : "r"(a));
}
__device__ __forceinline__ void ldsm_x2t(u32& r0, u32& r1, u32 a) {
    asm volatile("ldmatrix.sync.aligned.m8n8.x2.trans.shared.b16 {%0,%1}, [%2];"
                 : "=r"(r0), "=r"(r1) : "r"(a));
}
__device__ __forceinline__ void mma_f16(float* c, const u32* a, const u32* b) {
    asm volatile(
        "mma.sync.aligned.m16n8k16.row.col.f32.f16.f16.f32 "
        "{%0,%1,%2,%3}, {%4,%5,%6,%7}, {%8,%9}, {%0,%1,%2,%3};"
        : "+f"(c[0]), "+f"(c[1]), "+f"(c[2]), "+f"(c[3])
        : "r"(a[0]), "r"(a[1]), "r"(a[2]), "r"(a[3]), "r"(b[0]), "r"(b[1]));
}

// ---------------------------------------------------------------------------
// GEMM: D[m,n] = sum_k A[m,k]*B'[k,n]
//   BTERMS=2: B = Bhi + Blo (dual fp16);   BTERMS=1: B = Bhi only
//   BT=true : B stored [N][K] -> ldmatrix; BT=false: B [K][N] -> ldmatrix.trans
//   MODE 0: single fp16 out + bias;  MODE 2: fp32 out * alpha
// CTA tile 128x128, BK=64, 3-stage cp.async pipeline, 256 threads (8 warps
// 2x4), register frag double-buffering.
// ---------------------------------------------------------------------------
#define BM 128
#define BN 128
#define BKK 64
#define APITCH 72                            // 64 + 8 pad (16b units)
#define ABYTES (BM * APITCH * 2)             // 18432
#define BPITCH_T 72
#define BBYTES_T (BN * BPITCH_T * 2)         // 18432
#define BPITCH_N 136                         // 128 + 8 pad
#define BBYTES_N (BKK * BPITCH_N * 2)        // 17408

template <int MODE, bool BT, int BTERMS>
__global__ void __launch_bounds__(256, 1)
gemm_mma(const h16* __restrict__ A,
         const h16* __restrict__ Bhi, const h16* __restrict__ Blo,
         const float* __restrict__ bias,
         h16* __restrict__ C0, float* __restrict__ Cf,
         int lda, int ldb, int ldc, int K, float alpha,
         long long sA, long long sB, long long sC)
{
    constexpr int BBYTES  = BT ? BBYTES_T : BBYTES_N;
    constexpr int OFF_BHI = ABYTES;
    constexpr int OFF_BLO = ABYTES + BBYTES;
    constexpr int STAGE   = ABYTES + BTERMS * BBYTES;

    extern __shared__ char smem[];
    const u32 sb = smem_u32(smem);

    const int tid  = threadIdx.x;
    const int wid  = tid >> 5, lane = tid & 31;
    const int wm   = wid & 1, wn = wid >> 1;          // 2 x 4 warp grid
    const long long z = blockIdx.z;
    A += z * sA;
    Bhi += z * sB; if (BTERMS == 2) Blo += z * sB;

    const int m0 = blockIdx.y * BM;
    const int n0 = blockIdx.x * BN;

    // ---- loader geometry (BK=64, 256 threads) ----
    const int ar0 = tid >> 2, ac = (tid & 3) * 16;
    const int nr0 = tid >> 4, nc = (tid & 15) * 8;

    auto load_stage = [&](int t) {
        const long long kb = (long long)t * BKK;
        const u32 st = sb + (u32)((t % 3) * STAGE);
#pragma unroll
        for (int i = 0; i < 2; i++) {
            const int r = ar0 + i * 64;
            const long long g = (long long)(m0 + r) * lda + kb + ac;
            const u32 d = st + (u32)(r * APITCH + ac) * 2;
            CP_ASYNC16(d,      A + g);
            CP_ASYNC16(d + 16, A + g + 8);
        }
        if (BT) {
#pragma unroll
            for (int i = 0; i < 2; i++) {
                const int r = ar0 + i * 64;
                const long long g = (long long)(n0 + r) * ldb + kb + ac;
                const u32 d = st + OFF_BHI + (u32)(r * BPITCH_T + ac) * 2;
                CP_ASYNC16(d,      Bhi + g);
                CP_ASYNC16(d + 16, Bhi + g + 8);
                if (BTERMS == 2) {
                    CP_ASYNC16(d + BBYTES,      Blo + g);
                    CP_ASYNC16(d + BBYTES + 16, Blo + g + 8);
                }
            }
        } else {
#pragma unroll
            for (int i = 0; i < 4; i++) {
                const int r = nr0 + i * 16;
                const long long g = (kb + r) * (long long)ldb + n0 + nc;
                const u32 d = st + OFF_BHI + (u32)(r * BPITCH_N + nc) * 2;
                CP_ASYNC16(d, Bhi + g);
                if (BTERMS == 2) CP_ASYNC16(d + BBYTES, Blo + g);
            }
        }
    };

    // ---- ldmatrix per-lane offsets ----
    const int a_lr = (lane & 7) + ((lane >> 3) & 1) * 8;
    const int a_lk = (lane >> 4) * 8;
    u32 a_off[4];
#pragma unroll
    for (int mt = 0; mt < 4; mt++)
        a_off[mt] = (u32)((wm * 64 + mt * 16 + a_lr) * APITCH + a_lk) * 2;

    const int l16 = lane & 15;
    u32 b_off[4];
    if (BT) {
        const int b_nr = l16 & 7, b_k = (l16 >> 3) * 8;
#pragma unroll
        for (int nt = 0; nt < 4; nt++)
            b_off[nt] = (u32)((wn * 32 + nt * 8 + b_nr) * BPITCH_T + b_k) * 2;
    } else {
        const int b_kr = l16;      // 16 k-rows
#pragma unroll
        for (int nt = 0; nt < 4; nt++)
            b_off[nt] = (u32)(b_kr * BPITCH_N + wn * 32 + nt * 8) * 2;
    }

    float acc[4][4][4];
#pragma unroll
    for (int i = 0; i < 4; i++)
#pragma unroll
        for (int j = 0; j < 4; j++)
#pragma unroll
            for (int v = 0; v < 4; v++) acc[i][j][v] = 0.0f;

    // double-buffered fragments
    u32 ah[2][4][4], bh[2][4][2], bl[2][4][2];

    const int nst = K / BKK;

    load_stage(0); CP_COMMIT();
    load_stage(1); CP_COMMIT();

    for (int t = 0; t < nst; t++) {
        CP_WAIT1();
        __syncthreads();
        if (t + 2 < nst) load_stage(t + 2);
        CP_COMMIT();

        const u32 st  = sb + (u32)((t % 3) * STAGE);
        const u32 bAh = st;
        const u32 bBh = st + OFF_BHI, bBl = st + OFF_BLO;

        // prime frag buffer 0 (kk = 0)
        {
#pragma unroll
            for (int mt = 0; mt < 4; mt++)
                ldsm_x4(ah[0][mt][0], ah[0][mt][1], ah[0][mt][2], ah[0][mt][3],
                        bAh + a_off[mt]);
#pragma unroll
            for (int nt = 0; nt < 4; nt++) {
                if (BT) {
                    ldsm_x2(bh[0][nt][0], bh[0][nt][1], bBh + b_off[nt]);
                    if (BTERMS == 2)
                        ldsm_x2(bl[0][nt][0], bl[0][nt][1], bBl + b_off[nt]);
                } else {
                    ldsm_x2t(bh[0][nt][0], bh[0][nt][1], bBh + b_off[nt]);
                    if (BTERMS == 2)
                        ldsm_x2t(bl[0][nt][0], bl[0][nt][1], bBl + b_off[nt]);
                }
            }
        }

#pragma unroll
        for (int kk = 0; kk < 4; kk++) {
            const int cur = kk & 1, nxt = cur ^ 1;
            if (kk < 3) {
                const u32 ak = (u32)((kk + 1) * 32);
                const u32 bk = BT ? (u32)((kk + 1) * 32)
                                  : (u32)((kk + 1) * 16 * BPITCH_N * 2);
#pragma unroll
                for (int mt = 0; mt < 4; mt++)
                    ldsm_x4(ah[nxt][mt][0], ah[nxt][mt][1], ah[nxt][mt][2],
                            ah[nxt][mt][3], bAh + a_off[mt] + ak);
#pragma unroll
                for (int nt = 0; nt < 4; nt++) {
                    if (BT) {
                        ldsm_x2(bh[nxt][nt][0], bh[nxt][nt][1], bBh + b_off[nt] + bk);
                        if (BTERMS == 2)
                            ldsm_x2(bl[nxt][nt][0], bl[nxt][nt][1], bBl + b_off[nt] + bk);
                    } else {
                        ldsm_x2t(bh[nxt][nt][0], bh[nxt][nt][1], bBh + b_off[nt] + bk);
                        if (BTERMS == 2)
                            ldsm_x2t(bl[nxt][nt][0], bl[nxt][nt][1], bBl + b_off[nt] + bk);
                    }
                }
            }
#pragma unroll
            for (int mt = 0; mt < 4; mt++)
#pragma unroll
                for (int nt = 0; nt < 4; nt++) {
                    mma_f16(acc[mt][nt], ah[cur][mt], bh[cur][nt]);
                    if (BTERMS == 2)
                        mma_f16(acc[mt][nt], ah[cur][mt], bl[cur][nt]);
                }
        }
    }

    // ---- epilogue ----
    const int gr = lane >> 2, gc = (lane & 3) * 2;
#pragma unroll
    for (int mt = 0; mt < 4; mt++) {
#pragma unroll
        for (int nt = 0; nt < 4; nt++) {
            const int m_ = m0 + wm * 64 + mt * 16 + gr;
            const int n_ = n0 + wn * 32 + nt * 8 + gc;
            const float* a4 = acc[mt][nt];
            if (MODE == 0) {
                const float b0 = bias[n_], b1 = bias[n_ + 1];
#pragma unroll
                for (int h = 0; h < 2; h++) {
                    const float v0 = a4[2 * h]     + b0;
                    const float v1 = a4[2 * h + 1] + b1;
                    const long long o = (long long)(m_ + 8 * h) * ldc + n_;
                    h16 hp[2] = { __half_as_ushort(__float2half_rn(v0)),
                                  __half_as_ushort(__float2half_rn(v1)) };
                    *(u32*)(C0 + o) = *(const u32*)hp;
                }
            } else {
                float* Cz = Cf + z * sC;
#pragma unroll
                for (int h = 0; h < 2; h++) {
                    const long long o = (long long)(m_ + 8 * h) * ldc + n_;
                    float2 v = make_float2(a4[2 * h] * alpha, a4[2 * h + 1] * alpha);
                    *(float2*)(Cz + o) = v;
                }
            }
        }
    }
}

// ---------------------------------------------------------------------------
// fp32 -> single fp16 conversion (projection activations)
// ---------------------------------------------------------------------------
__global__ void __launch_bounds__(256)
conv_f16(const float4* __restrict__ in, h16* __restrict__ out)
{
    const long long i = (long long)blockIdx.x * 256 + threadIdx.x;
    const float4 v = in[i];
    h16 p[4] = { __half_as_ushort(__float2half_rn(v.x)),
                 __half_as_ushort(__float2half_rn(v.y)),
                 __half_as_ushort(__float2half_rn(v.z)),
                 __half_as_ushort(__float2half_rn(v.w)) };
    *(uint2*)&out[i * 4] = *(const uint2*)p;
}

// W [F=1024, H=1024] -> W^T split hi/lo fp16 [H, F]
__global__ void wt_split(const float* __restrict__ W, h16* __restrict__ Thi,
                         h16* __restrict__ Tlo)
{
    __shared__ float ts[32][33];
    const int tx = threadIdx.x, ty = threadIdx.y;
    ts[ty][tx] = W[(long long)(blockIdx.y * 32 + ty) * 1024 + blockIdx.x * 32 + tx];
    __syncthreads();
    const float x = ts[tx][ty];
    const long long o = (long long)(blockIdx.x * 32 + ty) * 1024 + blockIdx.y * 32 + tx;
    const __half h = __float2half_rn(x);
    Thi[o] = __half_as_ushort(h);
    Tlo[o] = __half_as_ushort(__float2half_rn(x - __half2float(h)));
}

// ---------------------------------------------------------------------------
// Mask dtype detection (bool may arrive as u8/i32/f32)
// ---------------------------------------------------------------------------
__global__ void detect_mask_kernel(const unsigned char* __restrict__ m)
{
    __shared__ int bad_i32, bad_f32;
    if (threadIdx.x == 0) { bad_i32 = 0; bad_f32 = 0; }
    __syncthreads();
    const unsigned int* w = (const unsigned int*)m;
    for (int i = threadIdx.x; i < 2048; i += 256) {
        unsigned int x = w[i];
        if (x != 0u && x != 1u)          bad_i32 = 1;
        if (x != 0u && x != 0x3F800000u) bad_f32 = 1;
    }
    __syncthreads();
    if (threadIdx.x == 0)
        g_mask_mode = bad_i32 ? (bad_f32 ? 0 : 2) : 1;
}

// ---------------------------------------------------------------------------
// Masked softmax over rows of S [B*TQ, 2048] -> P single fp16
// ---------------------------------------------------------------------------
__global__ void __launch_bounds__(256)
softmax_kernel(const float* __restrict__ S, const void* __restrict__ maskv,
               h16* __restrict__ P)
{
    const int TK = 2048;
    const long long base = (long long)blockIdx.x * TK;
    const float* s = S + base;
    const int tid  = threadIdx.x;
    const int mode = g_mask_mode;

    float v[8];
    bool  keep[8];
#pragma unroll
    for (int i = 0; i < 8; i++) {
        const int idx = tid + i * 256;
        v[i] = s[idx];
        bool kp;
        if (mode == 1)      kp = ((const int*)maskv)[base + idx] != 0;
        else if (mode == 2) kp = ((const float*)maskv)[base + idx] != 0.0f;
        else                kp = ((const unsigned char*)maskv)[base + idx] != 0;
        keep[i] = kp;
    }

    float mx = -3.0e38f;
#pragma unroll
    for (int i = 0; i < 8; i++)
        if (keep[i]) mx = fmaxf(mx, v[i]);

    __shared__ float red[8];
#pragma unroll
    for (int o = 16; o > 0; o >>= 1)
        mx = fmaxf(mx, __shfl_xor_sync(0xffffffffu, mx, o));
    if ((tid & 31) == 0) red[tid >> 5] = mx;
    __syncthreads();
    float bm = red[0];
#pragma unroll
    for (int i = 1; i < 8; i++) bm = fmaxf(bm, red[i]);

    float sum = 0.0f;
#pragma unroll
    for (int i = 0; i < 8; i++) {
        const float e = keep[i] ? __expf(v[i] - bm) : 0.0f;
        v[i] = e;
        sum += e;
    }
#pragma unroll
    for (int o = 16; o > 0; o >>= 1)
        sum += __shfl_xor_sync(0xffffffffu, sum, o);
    __syncthreads();
    if ((tid & 31) == 0) red[tid >> 5] = sum;
    __syncthreads();
    float ts = 0.0f;
#pragma unroll
    for (int i = 0; i < 8; i++) ts += red[i];

    const float inv = 1.0f / ts;
#pragma unroll
    for (int i = 0; i < 8; i++)
        P[base + tid + i * 256] =
            __half_as_ushort(__float2half_rn(v[i] * inv));
}

// ---------------------------------------------------------------------------
// kernel_launch
// ---------------------------------------------------------------------------
extern "C" void kernel_launch(void* const* d_in, const int* in_sizes, int n_in,
                              void* d_out, int out_size)
{
    (void)in_sizes; (void)n_in; (void)out_size;

    const float* query = (const float*)d_in[0];
    const float* enc   = (const float*)d_in[1];
    const unsigned char* mask = (const unsigned char*)d_in[2];
    const float* Wq = (const float*)d_in[3];
    const float* bq = (const float*)d_in[4];
    const float* Wk = (const float*)d_in[5];
    const float* bk = (const float*)d_in[6];
    const float* Wv = (const float*)d_in[7];
    const float* bv = (const float*)d_in[8];
    float* out = (float*)d_out;

    h16 *Ef, *Xf;
    h16 *Wqh, *Wql, *Wkh, *Wkl, *Wvh, *Wvl;
    h16 *Q, *K, *V, *P;
    float* Sp;
    cudaGetSymbolAddress((void**)&Ef,  g_Ef);
    cudaGetSymbolAddress((void**)&Xf,  g_Xf);
    cudaGetSymbolAddress((void**)&Wqh, g_Wq_hi); cudaGetSymbolAddress((void**)&Wql, g_Wq_lo);
    cudaGetSymbolAddress((void**)&Wkh, g_Wk_hi); cudaGetSymbolAddress((void**)&Wkl, g_Wk_lo);
    cudaGetSymbolAddress((void**)&Wvh, g_Wv_hi); cudaGetSymbolAddress((void**)&Wvl, g_Wv_lo);
    cudaGetSymbolAddress((void**)&Q,   g_Q);
    cudaGetSymbolAddress((void**)&K,   g_K);
    cudaGetSymbolAddress((void**)&V,   g_V);
    cudaGetSymbolAddress((void**)&P,   g_P);
    cudaGetSymbolAddress((void**)&Sp,  g_S);

    constexpr int SMEM_PROJ = 3 * (ABYTES + 2 * BBYTES_T);   // 165888
    constexpr int SMEM_SC   = 3 * (ABYTES + 1 * BBYTES_T);   // 110592
    constexpr int SMEM_PV   = 3 * (ABYTES + 1 * BBYTES_N);   // 107520
    cudaFuncSetAttribute(gemm_mma<0, true, 2>,
                         cudaFuncAttributeMaxDynamicSharedMemorySize, SMEM_PROJ);
    cudaFuncSetAttribute(gemm_mma<2, true, 1>,
                         cudaFuncAttributeMaxDynamicSharedMemorySize, SMEM_SC);
    cudaFuncSetAttribute(gemm_mma<2, false, 1>,
                         cudaFuncAttributeMaxDynamicSharedMemorySize, SMEM_PV);

    const int T = 2048;

    // 1) convert activations to single fp16
    conv_f16<<<16384, 256>>>((const float4*)enc,   Ef);
    conv_f16<<<16384, 256>>>((const float4*)query, Xf);

    // 2) transpose+split weights (fp16 hi/lo)
    dim3 wtg(32, 32), wtb(32, 32);
    wt_split<<<wtg, wtb>>>(Wq, Wqh, Wql);
    wt_split<<<wtg, wtb>>>(Wk, Wkh, Wkl);
    wt_split<<<wtg, wtb>>>(Wv, Wvh, Wvl);

    detect_mask_kernel<<<1, 256>>>(mask);

    // 3) projections: fp16 2-term weights, single fp16 outputs
    dim3 gp(1024 / BN, 16384 / BM, 1);
    gemm_mma<0, true, 2><<<gp, 256, SMEM_PROJ>>>(Ef, Wkh, Wkl, bk,
        K, nullptr, 1024, 1024, 1024, 1024, 1.0f, 0, 0, 0);
    gemm_mma<0, true, 2><<<gp, 256, SMEM_PROJ>>>(Ef, Wvh, Wvl, bv,
        V, nullptr, 1024, 1024, 1024, 1024, 1.0f, 0, 0, 0);
    gemm_mma<0, true, 2><<<gp, 256, SMEM_PROJ>>>(Xf, Wqh, Wql, bq,
        Q, nullptr, 1024, 1024, 1024, 1024, 1.0f, 0, 0, 0);

    // 4) scores: fp16 1-term, S = (Q K^T) / 32
    dim3 gs(T / BN, T / BM, 8);
    gemm_mma<2, true, 1><<<gs, 256, SMEM_SC>>>(Q, K, nullptr, nullptr,
        nullptr, Sp, 1024, 1024, 2048, 1024, 0.03125f,
        2048LL * 1024, 2048LL * 1024, 2048LL * 2048);

    // 5) masked softmax -> P single fp16
    softmax_kernel<<<8 * T, 256>>>(Sp, (const void*)mask, P);

    // 6) output: fp16 1-term, O = P V   (V NN layout, ldmatrix.trans)
    dim3 go(1024 / BN, T / BM, 8);
    gemm_mma<2, false, 1><<<go, 256, SMEM_PV>>>(P, V, nullptr, nullptr,
        nullptr, out, 2048, 1024, 1024, 2048, 1.0f,
        2048LL * 2048, 2048LL * 1024, 2048LL * 1024);
}

// round 11
// speedup vs baseline: 2.3890x; 1.2448x over previous
#include <cuda_runtime.h>
#include <cuda_fp16.h>

typedef unsigned short h16;    // opaque 16-bit payload (fp16 bits)
typedef unsigned int u32;
typedef unsigned long long u64;

// ---------------------------------------------------------------------------
// Problem constants: B=8, TQ=TK=2048, F=1024, H=1024
// ---------------------------------------------------------------------------
#define MTOT (16384LL * 1024)

static __device__ h16   g_Ef[MTOT];                           // encoder fp16
static __device__ h16   g_Xf[MTOT];                           // query fp16
static __device__ h16   g_Wq[1024*1024];                      // W^T fp16
static __device__ h16   g_Wk[1024*1024];
static __device__ h16   g_Wv[1024*1024];
static __device__ h16   g_Q[MTOT];                            // fp16
static __device__ h16   g_K[MTOT];                            // fp16
static __device__ h16   g_V[MTOT];                            // fp16 [b*2048+t][1024]
static __device__ float g_S[8LL * 2048 * 2048];
static __device__ h16   g_P[8LL * 2048 * 2048];               // fp16
static __device__ int   g_mask_mode;

// ---------------------------------------------------------------------------
// PTX helpers (sm_80-era; legal under generic compute_103 target)
// ---------------------------------------------------------------------------
__device__ __forceinline__ u32 smem_u32(const void* p) {
    u32 a;
    asm("{ .reg .u64 t; cvta.to.shared.u64 t, %1; cvt.u32.u64 %0, t; }"
        : "=r"(a) : "l"(p));
    return a;
}
#define CP_ASYNC16(dst, src) \
    asm volatile("cp.async.cg.shared.global [%0], [%1], 16;" \
                 :: "r"(dst), "l"(src) : "memory")
#define CP_COMMIT() asm volatile("cp.async.commit_group;" ::: "memory")
#define CP_WAIT1()  asm volatile("cp.async.wait_group 1;" ::: "memory")

__device__ __forceinline__ void ldsm_x4(u32& r0, u32& r1, u32& r2, u32& r3, u32 a) {
    asm volatile("ldmatrix.sync.aligned.m8n8.x4.shared.b16 {%0,%1,%2,%3}, [%4];"
                 : "=r"(r0), "=r"(r1), "=r"(r2), "=r"(r3) : "r"(a));
}
__device__ __forceinline__ void ldsm_x2(u32& r0, u32& r1, u32 a) {
    asm volatile("ldmatrix.sync.aligned.m8n8.x2.shared.b16 {%0,%1}, [%2];"
                 : "=r"(r0), "=r"(r1) : "r"(a));
}
__device__ __forceinline__ void ldsm_x2t(u32& r0, u32& r1, u32 a) {
    asm volatile("ldmatrix.sync.aligned.m8n8.x2.trans.shared.b16 {%0,%1}, [%2];"
                 : "=r"(r0), "=r"(r1) : "r"(a));
}
__device__ __forceinline__ void mma_f16(float* c, const u32* a, const u32* b) {
    asm volatile(
        "mma.sync.aligned.m16n8k16.row.col.f32.f16.f16.f32 "
        "{%0,%1,%2,%3}, {%4,%5,%6,%7}, {%8,%9}, {%0,%1,%2,%3};"
        : "+f"(c[0]), "+f"(c[1]), "+f"(c[2]), "+f"(c[3])
        : "r"(a[0]), "r"(a[1]), "r"(a[2]), "r"(a[3]), "r"(b[0]), "r"(b[1]));
}

// ---------------------------------------------------------------------------
// GEMM: D[m,n] = sum_k A[m,k]*B'[k,n]   (pure fp16, 1 MMA per k-tile)
//   BT=true : B stored [N][K] -> ldmatrix; BT=false: B [K][N] -> ldmatrix.trans
//   MODE 0: single fp16 out + bias;  MODE 2: fp32 out * alpha
// CTA tile 128x128, BK=64, 3-stage cp.async pipeline, 256 threads (8 warps
// 2x4), register frag double-buffering.
// ---------------------------------------------------------------------------
#define BM 128
#define BN 128
#define BKK 64
#define APITCH 72                            // 64 + 8 pad (16b units)
#define ABYTES (BM * APITCH * 2)             // 18432
#define BPITCH_T 72
#define BBYTES_T (BN * BPITCH_T * 2)         // 18432
#define BPITCH_N 136                         // 128 + 8 pad
#define BBYTES_N (BKK * BPITCH_N * 2)        // 17408

template <int MODE, bool BT>
__global__ void __launch_bounds__(256, 1)
gemm_mma(const h16* __restrict__ A, const h16* __restrict__ B,
         const float* __restrict__ bias,
         h16* __restrict__ C0, float* __restrict__ Cf,
         int lda, int ldb, int ldc, int K, float alpha,
         long long sA, long long sB, long long sC)
{
    constexpr int BBYTES  = BT ? BBYTES_T : BBYTES_N;
    constexpr int OFF_B   = ABYTES;
    constexpr int STAGE   = ABYTES + BBYTES;

    extern __shared__ char smem[];
    const u32 sb = smem_u32(smem);

    const int tid  = threadIdx.x;
    const int wid  = tid >> 5, lane = tid & 31;
    const int wm   = wid & 1, wn = wid >> 1;          // 2 x 4 warp grid
    const long long z = blockIdx.z;
    A += z * sA;
    B += z * sB;

    const int m0 = blockIdx.y * BM;
    const int n0 = blockIdx.x * BN;

    // ---- loader geometry (BK=64, 256 threads) ----
    const int ar0 = tid >> 2, ac = (tid & 3) * 16;
    const int nr0 = tid >> 4, nc = (tid & 15) * 8;

    auto load_stage = [&](int t) {
        const long long kb = (long long)t * BKK;
        const u32 st = sb + (u32)((t % 3) * STAGE);
#pragma unroll
        for (int i = 0; i < 2; i++) {
            const int r = ar0 + i * 64;
            const long long g = (long long)(m0 + r) * lda + kb + ac;
            const u32 d = st + (u32)(r * APITCH + ac) * 2;
            CP_ASYNC16(d,      A + g);
            CP_ASYNC16(d + 16, A + g + 8);
        }
        if (BT) {
#pragma unroll
            for (int i = 0; i < 2; i++) {
                const int r = ar0 + i * 64;
                const long long g = (long long)(n0 + r) * ldb + kb + ac;
                const u32 d = st + OFF_B + (u32)(r * BPITCH_T + ac) * 2;
                CP_ASYNC16(d,      B + g);
                CP_ASYNC16(d + 16, B + g + 8);
            }
        } else {
#pragma unroll
            for (int i = 0; i < 4; i++) {
                const int r = nr0 + i * 16;
                const long long g = (kb + r) * (long long)ldb + n0 + nc;
                const u32 d = st + OFF_B + (u32)(r * BPITCH_N + nc) * 2;
                CP_ASYNC16(d, B + g);
            }
        }
    };

    // ---- ldmatrix per-lane offsets ----
    const int a_lr = (lane & 7) + ((lane >> 3) & 1) * 8;
    const int a_lk = (lane >> 4) * 8;
    u32 a_off[4];
#pragma unroll
    for (int mt = 0; mt < 4; mt++)
        a_off[mt] = (u32)((wm * 64 + mt * 16 + a_lr) * APITCH + a_lk) * 2;

    const int l16 = lane & 15;
    u32 b_off[4];
    if (BT) {
        const int b_nr = l16 & 7, b_k = (l16 >> 3) * 8;
#pragma unroll
        for (int nt = 0; nt < 4; nt++)
            b_off[nt] = (u32)((wn * 32 + nt * 8 + b_nr) * BPITCH_T + b_k) * 2;
    } else {
        const int b_kr = l16;      // 16 k-rows
#pragma unroll
        for (int nt = 0; nt < 4; nt++)
            b_off[nt] = (u32)(b_kr * BPITCH_N + wn * 32 + nt * 8) * 2;
    }

    float acc[4][4][4];
#pragma unroll
    for (int i = 0; i < 4; i++)
#pragma unroll
        for (int j = 0; j < 4; j++)
#pragma unroll
            for (int v = 0; v < 4; v++) acc[i][j][v] = 0.0f;

    // double-buffered fragments
    u32 ah[2][4][4], bh[2][4][2];

    const int nst = K / BKK;

    load_stage(0); CP_COMMIT();
    load_stage(1); CP_COMMIT();

    for (int t = 0; t < nst; t++) {
        CP_WAIT1();
        __syncthreads();
        if (t + 2 < nst) load_stage(t + 2);
        CP_COMMIT();

        const u32 st  = sb + (u32)((t % 3) * STAGE);
        const u32 bAh = st;
        const u32 bBh = st + OFF_B;

        // prime frag buffer 0 (kk = 0)
        {
#pragma unroll
            for (int mt = 0; mt < 4; mt++)
                ldsm_x4(ah[0][mt][0], ah[0][mt][1], ah[0][mt][2], ah[0][mt][3],
                        bAh + a_off[mt]);
#pragma unroll
            for (int nt = 0; nt < 4; nt++) {
                if (BT) ldsm_x2(bh[0][nt][0], bh[0][nt][1], bBh + b_off[nt]);
                else    ldsm_x2t(bh[0][nt][0], bh[0][nt][1], bBh + b_off[nt]);
            }
        }

#pragma unroll
        for (int kk = 0; kk < 4; kk++) {
            const int cur = kk & 1, nxt = cur ^ 1;
            if (kk < 3) {
                const u32 ak = (u32)((kk + 1) * 32);
                const u32 bk = BT ? (u32)((kk + 1) * 32)
                                  : (u32)((kk + 1) * 16 * BPITCH_N * 2);
#pragma unroll
                for (int mt = 0; mt < 4; mt++)
                    ldsm_x4(ah[nxt][mt][0], ah[nxt][mt][1], ah[nxt][mt][2],
                            ah[nxt][mt][3], bAh + a_off[mt] + ak);
#pragma unroll
                for (int nt = 0; nt < 4; nt++) {
                    if (BT) ldsm_x2(bh[nxt][nt][0], bh[nxt][nt][1], bBh + b_off[nt] + bk);
                    else    ldsm_x2t(bh[nxt][nt][0], bh[nxt][nt][1], bBh + b_off[nt] + bk);
                }
            }
#pragma unroll
            for (int mt = 0; mt < 4; mt++)
#pragma unroll
                for (int nt = 0; nt < 4; nt++)
                    mma_f16(acc[mt][nt], ah[cur][mt], bh[cur][nt]);
        }
    }

    // ---- epilogue ----
    const int gr = lane >> 2, gc = (lane & 3) * 2;
#pragma unroll
    for (int mt = 0; mt < 4; mt++) {
#pragma unroll
        for (int nt = 0; nt < 4; nt++) {
            const int m_ = m0 + wm * 64 + mt * 16 + gr;
            const int n_ = n0 + wn * 32 + nt * 8 + gc;
            const float* a4 = acc[mt][nt];
            if (MODE == 0) {
                const float b0 = bias[n_], b1 = bias[n_ + 1];
#pragma unroll
                for (int h = 0; h < 2; h++) {
                    const float v0 = a4[2 * h]     + b0;
                    const float v1 = a4[2 * h + 1] + b1;
                    const long long o = (long long)(m_ + 8 * h) * ldc + n_;
                    h16 hp[2] = { __half_as_ushort(__float2half_rn(v0)),
                                  __half_as_ushort(__float2half_rn(v1)) };
                    *(u32*)(C0 + o) = *(const u32*)hp;
                }
            } else {
                float* Cz = Cf + z * sC;
#pragma unroll
                for (int h = 0; h < 2; h++) {
                    const long long o = (long long)(m_ + 8 * h) * ldc + n_;
                    float2 v = make_float2(a4[2 * h] * alpha, a4[2 * h + 1] * alpha);
                    *(float2*)(Cz + o) = v;
                }
            }
        }
    }
}

// ---------------------------------------------------------------------------
// fp32 -> single fp16 conversion (projection activations)
// ---------------------------------------------------------------------------
__global__ void __launch_bounds__(256)
conv_f16(const float4* __restrict__ in, h16* __restrict__ out)
{
    const long long i = (long long)blockIdx.x * 256 + threadIdx.x;
    const float4 v = in[i];
    h16 p[4] = { __half_as_ushort(__float2half_rn(v.x)),
                 __half_as_ushort(__float2half_rn(v.y)),
                 __half_as_ushort(__float2half_rn(v.z)),
                 __half_as_ushort(__float2half_rn(v.w)) };
    *(uint2*)&out[i * 4] = *(const uint2*)p;
}

// W [F=1024, H=1024] -> W^T single fp16 [H, F]
__global__ void wt_conv(const float* __restrict__ W, h16* __restrict__ T)
{
    __shared__ float ts[32][33];
    const int tx = threadIdx.x, ty = threadIdx.y;
    ts[ty][tx] = W[(long long)(blockIdx.y * 32 + ty) * 1024 + blockIdx.x * 32 + tx];
    __syncthreads();
    const float x = ts[tx][ty];
    const long long o = (long long)(blockIdx.x * 32 + ty) * 1024 + blockIdx.y * 32 + tx;
    T[o] = __half_as_ushort(__float2half_rn(x));
}

// ---------------------------------------------------------------------------
// Mask dtype detection (bool may arrive as u8/i32/f32)
// ---------------------------------------------------------------------------
__global__ void detect_mask_kernel(const unsigned char* __restrict__ m)
{
    __shared__ int bad_i32, bad_f32;
    if (threadIdx.x == 0) { bad_i32 = 0; bad_f32 = 0; }
    __syncthreads();
    const unsigned int* w = (const unsigned int*)m;
    for (int i = threadIdx.x; i < 2048; i += 256) {
        unsigned int x = w[i];
        if (x != 0u && x != 1u)          bad_i32 = 1;
        if (x != 0u && x != 0x3F800000u) bad_f32 = 1;
    }
    __syncthreads();
    if (threadIdx.x == 0)
        g_mask_mode = bad_i32 ? (bad_f32 ? 0 : 2) : 1;
}

// ---------------------------------------------------------------------------
// Masked softmax over rows of S [B*TQ, 2048] -> P single fp16
// ---------------------------------------------------------------------------
__global__ void __launch_bounds__(256)
softmax_kernel(const float* __restrict__ S, const void* __restrict__ maskv,
               h16* __restrict__ P)
{
    const int TK = 2048;
    const long long base = (long long)blockIdx.x * TK;
    const float* s = S + base;
    const int tid  = threadIdx.x;
    const int mode = g_mask_mode;

    float v[8];
    bool  keep[8];
#pragma unroll
    for (int i = 0; i < 8; i++) {
        const int idx = tid + i * 256;
        v[i] = s[idx];
        bool kp;
        if (mode == 1)      kp = ((const int*)maskv)[base + idx] != 0;
        else if (mode == 2) kp = ((const float*)maskv)[base + idx] != 0.0f;
        else                kp = ((const unsigned char*)maskv)[base + idx] != 0;
        keep[i] = kp;
    }

    float mx = -3.0e38f;
#pragma unroll
    for (int i = 0; i < 8; i++)
        if (keep[i]) mx = fmaxf(mx, v[i]);

    __shared__ float red[8];
#pragma unroll
    for (int o = 16; o > 0; o >>= 1)
        mx = fmaxf(mx, __shfl_xor_sync(0xffffffffu, mx, o));
    if ((tid & 31) == 0) red[tid >> 5] = mx;
    __syncthreads();
    float bm = red[0];
#pragma unroll
    for (int i = 1; i < 8; i++) bm = fmaxf(bm, red[i]);

    float sum = 0.0f;
#pragma unroll
    for (int i = 0; i < 8; i++) {
        const float e = keep[i] ? __expf(v[i] - bm) : 0.0f;
        v[i] = e;
        sum += e;
    }
#pragma unroll
    for (int o = 16; o > 0; o >>= 1)
        sum += __shfl_xor_sync(0xffffffffu, sum, o);
    __syncthreads();
    if ((tid & 31) == 0) red[tid >> 5] = sum;
    __syncthreads();
    float ts = 0.0f;
#pragma unroll
    for (int i = 0; i < 8; i++) ts += red[i];

    const float inv = 1.0f / ts;
#pragma unroll
    for (int i = 0; i < 8; i++)
        P[base + tid + i * 256] =
            __half_as_ushort(__float2half_rn(v[i] * inv));
}

// ---------------------------------------------------------------------------
// kernel_launch
// ---------------------------------------------------------------------------
extern "C" void kernel_launch(void* const* d_in, const int* in_sizes, int n_in,
                              void* d_out, int out_size)
{
    (void)in_sizes; (void)n_in; (void)out_size;

    const float* query = (const float*)d_in[0];
    const float* enc   = (const float*)d_in[1];
    const unsigned char* mask = (const unsigned char*)d_in[2];
    const float* Wq = (const float*)d_in[3];
    const float* bq = (const float*)d_in[4];
    const float* Wk = (const float*)d_in[5];
    const float* bk = (const float*)d_in[6];
    const float* Wv = (const float*)d_in[7];
    const float* bv = (const float*)d_in[8];
    float* out = (float*)d_out;

    h16 *Ef, *Xf, *Wqt, *Wkt, *Wvt;
    h16 *Q, *K, *V, *P;
    float* Sp;
    cudaGetSymbolAddress((void**)&Ef,  g_Ef);
    cudaGetSymbolAddress((void**)&Xf,  g_Xf);
    cudaGetSymbolAddress((void**)&Wqt, g_Wq);
    cudaGetSymbolAddress((void**)&Wkt, g_Wk);
    cudaGetSymbolAddress((void**)&Wvt, g_Wv);
    cudaGetSymbolAddress((void**)&Q,   g_Q);
    cudaGetSymbolAddress((void**)&K,   g_K);
    cudaGetSymbolAddress((void**)&V,   g_V);
    cudaGetSymbolAddress((void**)&P,   g_P);
    cudaGetSymbolAddress((void**)&Sp,  g_S);

    constexpr int SMEM_T = 3 * (ABYTES + BBYTES_T);   // 110592
    constexpr int SMEM_N = 3 * (ABYTES + BBYTES_N);   // 107520
    cudaFuncSetAttribute(gemm_mma<0, true>,
                         cudaFuncAttributeMaxDynamicSharedMemorySize, SMEM_T);
    cudaFuncSetAttribute(gemm_mma<2, true>,
                         cudaFuncAttributeMaxDynamicSharedMemorySize, SMEM_T);
    cudaFuncSetAttribute(gemm_mma<2, false>,
                         cudaFuncAttributeMaxDynamicSharedMemorySize, SMEM_N);

    const int T = 2048;

    // 1) convert activations to single fp16
    conv_f16<<<16384, 256>>>((const float4*)enc,   Ef);
    conv_f16<<<16384, 256>>>((const float4*)query, Xf);

    // 2) transpose+convert weights (single fp16)
    dim3 wtg(32, 32), wtb(32, 32);
    wt_conv<<<wtg, wtb>>>(Wq, Wqt);
    wt_conv<<<wtg, wtb>>>(Wk, Wkt);
    wt_conv<<<wtg, wtb>>>(Wv, Wvt);

    detect_mask_kernel<<<1, 256>>>(mask);

    // 3) projections: pure fp16, single fp16 outputs
    dim3 gp(1024 / BN, 16384 / BM, 1);
    gemm_mma<0, true><<<gp, 256, SMEM_T>>>(Ef, Wkt, bk,
        K, nullptr, 1024, 1024, 1024, 1024, 1.0f, 0, 0, 0);
    gemm_mma<0, true><<<gp, 256, SMEM_T>>>(Ef, Wvt, bv,
        V, nullptr, 1024, 1024, 1024, 1024, 1.0f, 0, 0, 0);
    gemm_mma<0, true><<<gp, 256, SMEM_T>>>(Xf, Wqt, bq,
        Q, nullptr, 1024, 1024, 1024, 1024, 1.0f, 0, 0, 0);

    // 4) scores: S = (Q K^T) / 32
    dim3 gs(T / BN, T / BM, 8);
    gemm_mma<2, true><<<gs, 256, SMEM_T>>>(Q, K, nullptr,
        nullptr, Sp, 1024, 1024, 2048, 1024, 0.03125f,
        2048LL * 1024, 2048LL * 1024, 2048LL * 2048);

    // 5) masked softmax -> P single fp16
    softmax_kernel<<<8 * T, 256>>>(Sp, (const void*)mask, P);

    // 6) output: O = P V   (V NN layout, ldmatrix.trans)
    dim3 go(1024 / BN, T / BM, 8);
    gemm_mma<2, false><<<go, 256, SMEM_N>>>(P, V, nullptr,
        nullptr, out, 2048, 1024, 1024, 2048, 1.0f,
        2048LL * 2048, 2048LL * 1024, 2048LL * 1024);
}